// round 2
// baseline (speedup 1.0000x reference)
#include <cuda_runtime.h>
#include <cuda_bf16.h>
#include <math_constants.h>

// Shapes
#define BB 4
#define TQ 1024
#define DMODEL 2048
#define NHEADS 16
#define HDIM 128
#define CACHE 1024
#define MROWS (BB*TQ)          // 4096
#define INV_SCALE 0.08838834764831843f  // 1/sqrt(128)

// Output layout: [out (4*1024*2048)] [new_k (4*2048*2048)] [new_v (4*2048*2048)]
#define OUT_ELEMS   (BB*TQ*DMODEL)          // 8388608
#define NEWK_OFF    OUT_ELEMS
#define NEWV_OFF    (OUT_ELEMS + BB*2048*DMODEL)

// Scratch (static device allocations - allowed)
__device__ float g_qproj[MROWS*DMODEL];
__device__ float g_kproj[MROWS*DMODEL];
__device__ float g_vproj[MROWS*DMODEL];
__device__ float g_attn [MROWS*DMODEL];

// ---------------------------------------------------------------------------
// SGEMM: C[M,2048] = A[M,2048] @ W[2048,2048]^T + bias   (both K-major)
// 128x128 tile, BK=16, 256 threads, 8x8 micro-tile (split 4+4 halves)
// ---------------------------------------------------------------------------
__global__ __launch_bounds__(256, 2)
void sgemm_abt(const float* __restrict__ A, const float* __restrict__ W,
               const float* __restrict__ bias, float* __restrict__ C)
{
    __shared__ float As[16][128];
    __shared__ float Ws[16][128];

    const int bm = blockIdx.y * 128;
    const int bn = blockIdx.x * 128;
    const int tid = threadIdx.x;
    const int tx = tid & 15;       // column group
    const int ty = tid >> 4;       // row group

    float acc[8][8];
#pragma unroll
    for (int r = 0; r < 8; r++)
#pragma unroll
        for (int c = 0; c < 8; c++) acc[r][c] = 0.f;

    for (int k0 = 0; k0 < 2048; k0 += 16) {
#pragma unroll
        for (int q = 0; q < 2; q++) {
            int f = tid + 256*q;           // 0..511 float4 slots
            int row = f >> 2;              // 0..127
            int kq  = (f & 3) << 2;        // 0,4,8,12
            float4 va = *(const float4*)(A + (size_t)(bm+row)*2048 + k0 + kq);
            As[kq+0][row] = va.x; As[kq+1][row] = va.y;
            As[kq+2][row] = va.z; As[kq+3][row] = va.w;
            float4 vw = *(const float4*)(W + (size_t)(bn+row)*2048 + k0 + kq);
            Ws[kq+0][row] = vw.x; Ws[kq+1][row] = vw.y;
            Ws[kq+2][row] = vw.z; Ws[kq+3][row] = vw.w;
        }
        __syncthreads();

#pragma unroll
        for (int kk = 0; kk < 16; kk++) {
            float4 a0 = *(const float4*)&As[kk][ty*4];
            float4 a1 = *(const float4*)&As[kk][64 + ty*4];
            float4 b0 = *(const float4*)&Ws[kk][tx*4];
            float4 b1 = *(const float4*)&Ws[kk][64 + tx*4];
            float ar[8] = {a0.x,a0.y,a0.z,a0.w, a1.x,a1.y,a1.z,a1.w};
            float br[8] = {b0.x,b0.y,b0.z,b0.w, b1.x,b1.y,b1.z,b1.w};
#pragma unroll
            for (int r = 0; r < 8; r++)
#pragma unroll
                for (int c = 0; c < 8; c++)
                    acc[r][c] += ar[r]*br[c];
        }
        __syncthreads();
    }

    // epilogue (+bias), float4 stores
    float4 bia0 = *(const float4*)&bias[bn + tx*4];
    float4 bia1 = *(const float4*)&bias[bn + 64 + tx*4];
#pragma unroll
    for (int r = 0; r < 8; r++) {
        int rowoff = (r < 4) ? (ty*4 + r) : (64 + ty*4 + (r-4));
        float* crow = C + (size_t)(bm + rowoff)*2048 + bn;
        float4 w0 = make_float4(acc[r][0]+bia0.x, acc[r][1]+bia0.y,
                                acc[r][2]+bia0.z, acc[r][3]+bia0.w);
        float4 w1 = make_float4(acc[r][4]+bia1.x, acc[r][5]+bia1.y,
                                acc[r][6]+bia1.z, acc[r][7]+bia1.w);
        *(float4*)(crow + tx*4)      = w0;
        *(float4*)(crow + 64 + tx*4) = w1;
    }
}

// ---------------------------------------------------------------------------
// Flash attention (fp32): causal over cache only.
// BQ=64 x BKV=64, 256 threads. S micro-tile 4x4, O micro-tile 4x8.
// Shared: Qs[64][132], union{Kts[128][68], Vs[64][132]}, Ps[64][68]
// ---------------------------------------------------------------------------
#define QS_STRIDE 132
#define KT_STRIDE 68
#define PS_STRIDE 68
#define SMEM_Q   0
#define SMEM_KV  (64*QS_STRIDE)                 // 8448
#define SMEM_P   (SMEM_KV + 128*KT_STRIDE)      // 8448+8704 = 17152
#define ATTN_SMEM_FLOATS (SMEM_P + 64*PS_STRIDE) // 21504 -> 86016 B

__global__ __launch_bounds__(256)
void attn_kernel(const float* __restrict__ Q,
                 const float* __restrict__ Kc,
                 const float* __restrict__ Vc,
                 float* __restrict__ O)
{
    extern __shared__ float sm[];
    float* Qs  = sm + SMEM_Q;
    float* Kts = sm + SMEM_KV;   // [128][68] during S phase
    float* Vs  = sm + SMEM_KV;   // [64][132] during PV phase (union)
    float* Ps  = sm + SMEM_P;    // [64][68]

    const int tid = threadIdx.x;
    const int tx = tid & 15;
    const int ty = tid >> 4;
    const int qb = blockIdx.x;
    const int bh = blockIdx.y;
    const int b = bh >> 4, h = bh & 15;
    const int q0 = qb * 64;

    const float* Qbase = Q  + ((size_t)b*TQ    + q0)*DMODEL + h*HDIM;
    const float* Kbase = Kc + ((size_t)b*CACHE      )*DMODEL + h*HDIM;
    const float* Vbase = Vc + ((size_t)b*CACHE      )*DMODEL + h*HDIM;

    // load Q tile [64][128]
#pragma unroll
    for (int q = 0; q < 8; q++) {
        int f = tid + 256*q;          // 0..2047 float4 slots
        int row = f >> 5;             // 0..63
        int col = (f & 31) << 2;      // 0..124
        float4 v = *(const float4*)(Qbase + (size_t)row*DMODEL + col);
        *(float4*)&Qs[row*QS_STRIDE + col] = v;
    }
    __syncthreads();

    float m_old[4], lsum[4];
    float acc_o[4][8];
#pragma unroll
    for (int r = 0; r < 4; r++) {
        m_old[r] = -CUDART_INF_F; lsum[r] = 0.f;
#pragma unroll
        for (int c = 0; c < 8; c++) acc_o[r][c] = 0.f;
    }

    for (int kvb = 0; kvb <= qb; kvb++) {
        const int kv0 = kvb * 64;
        // load K tile transposed -> Kts[d][j]
#pragma unroll
        for (int q = 0; q < 8; q++) {
            int f = tid + 256*q;
            int row = f >> 5;             // j
            int col = (f & 31) << 2;      // d
            float4 v = *(const float4*)(Kbase + (size_t)(kv0+row)*DMODEL + col);
            Kts[(col+0)*KT_STRIDE + row] = v.x;
            Kts[(col+1)*KT_STRIDE + row] = v.y;
            Kts[(col+2)*KT_STRIDE + row] = v.z;
            Kts[(col+3)*KT_STRIDE + row] = v.w;
        }
        __syncthreads();

        // S = Q K^T : s[r][c], rows ty*4+r, cols tx*4+c
        float s[4][4];
#pragma unroll
        for (int r = 0; r < 4; r++)
#pragma unroll
            for (int c = 0; c < 4; c++) s[r][c] = 0.f;

#pragma unroll 8
        for (int d4 = 0; d4 < 32; d4++) {
            int d = d4 << 2;
            float4 a0 = *(const float4*)&Qs[(ty*4+0)*QS_STRIDE + d];
            float4 a1 = *(const float4*)&Qs[(ty*4+1)*QS_STRIDE + d];
            float4 a2 = *(const float4*)&Qs[(ty*4+2)*QS_STRIDE + d];
            float4 a3 = *(const float4*)&Qs[(ty*4+3)*QS_STRIDE + d];
            float4 b0 = *(const float4*)&Kts[(d+0)*KT_STRIDE + tx*4];
            float4 b1 = *(const float4*)&Kts[(d+1)*KT_STRIDE + tx*4];
            float4 b2 = *(const float4*)&Kts[(d+2)*KT_STRIDE + tx*4];
            float4 b3 = *(const float4*)&Kts[(d+3)*KT_STRIDE + tx*4];
            const float A0[4] = {a0.x,a0.y,a0.z,a0.w};
            const float A1[4] = {a1.x,a1.y,a1.z,a1.w};
            const float A2[4] = {a2.x,a2.y,a2.z,a2.w};
            const float A3[4] = {a3.x,a3.y,a3.z,a3.w};
            const float4 Bv[4] = {b0,b1,b2,b3};
#pragma unroll
            for (int i = 0; i < 4; i++) {
                s[0][0] += A0[i]*Bv[i].x; s[0][1] += A0[i]*Bv[i].y;
                s[0][2] += A0[i]*Bv[i].z; s[0][3] += A0[i]*Bv[i].w;
                s[1][0] += A1[i]*Bv[i].x; s[1][1] += A1[i]*Bv[i].y;
                s[1][2] += A1[i]*Bv[i].z; s[1][3] += A1[i]*Bv[i].w;
                s[2][0] += A2[i]*Bv[i].x; s[2][1] += A2[i]*Bv[i].y;
                s[2][2] += A2[i]*Bv[i].z; s[2][3] += A2[i]*Bv[i].w;
                s[3][0] += A3[i]*Bv[i].x; s[3][1] += A3[i]*Bv[i].y;
                s[3][2] += A3[i]*Bv[i].z; s[3][3] += A3[i]*Bv[i].w;
            }
        }

        // scale + causal mask (only diagonal block needs masking)
#pragma unroll
        for (int r = 0; r < 4; r++)
#pragma unroll
            for (int c = 0; c < 4; c++) s[r][c] *= INV_SCALE;
        if (kvb == qb) {
#pragma unroll
            for (int r = 0; r < 4; r++)
#pragma unroll
                for (int c = 0; c < 4; c++)
                    if (kv0 + tx*4 + c > q0 + ty*4 + r) s[r][c] = -1e30f;
        }

        // online softmax
        float p[4][4];
#pragma unroll
        for (int r = 0; r < 4; r++) {
            float t = fmaxf(fmaxf(s[r][0], s[r][1]), fmaxf(s[r][2], s[r][3]));
#pragma unroll
            for (int off = 1; off < 16; off <<= 1)
                t = fmaxf(t, __shfl_xor_sync(0xffffffffu, t, off, 16));
            float mnew = fmaxf(m_old[r], t);
            float alpha = __expf(m_old[r] - mnew);
            float rs = 0.f;
#pragma unroll
            for (int c = 0; c < 4; c++) {
                p[r][c] = __expf(s[r][c] - mnew);
                rs += p[r][c];
            }
#pragma unroll
            for (int off = 1; off < 16; off <<= 1)
                rs += __shfl_xor_sync(0xffffffffu, rs, off, 16);
            lsum[r] = lsum[r]*alpha + rs;
#pragma unroll
            for (int c = 0; c < 8; c++) acc_o[r][c] *= alpha;
            m_old[r] = mnew;
            *(float4*)&Ps[(ty*4+r)*PS_STRIDE + tx*4] =
                make_float4(p[r][0], p[r][1], p[r][2], p[r][3]);
        }
        __syncthreads();   // Kts reads done, Ps written

        // load V tile [64][132-strided]
#pragma unroll
        for (int q = 0; q < 8; q++) {
            int f = tid + 256*q;
            int row = f >> 5;
            int col = (f & 31) << 2;
            float4 v = *(const float4*)(Vbase + (size_t)(kv0+row)*DMODEL + col);
            *(float4*)&Vs[row*QS_STRIDE + col] = v;
        }
        __syncthreads();   // V ready

        // O += P @ V : rows ty*4+r, cols {tx*4..+3, 64+tx*4..+3}
#pragma unroll 4
        for (int j = 0; j < 64; j++) {
            float pv0 = Ps[(ty*4+0)*PS_STRIDE + j];
            float pv1 = Ps[(ty*4+1)*PS_STRIDE + j];
            float pv2 = Ps[(ty*4+2)*PS_STRIDE + j];
            float pv3 = Ps[(ty*4+3)*PS_STRIDE + j];
            float4 v0 = *(const float4*)&Vs[j*QS_STRIDE + tx*4];
            float4 v1 = *(const float4*)&Vs[j*QS_STRIDE + 64 + tx*4];
            const float V8[8] = {v0.x,v0.y,v0.z,v0.w, v1.x,v1.y,v1.z,v1.w};
            const float PV[4] = {pv0,pv1,pv2,pv3};
#pragma unroll
            for (int r = 0; r < 4; r++)
#pragma unroll
                for (int c = 0; c < 8; c++)
                    acc_o[r][c] += PV[r]*V8[c];
        }
        __syncthreads();   // PV done before next K load
    }

    // finalize + store to g_attn ([B,TQ,D] layout so O-projection reads it directly)
#pragma unroll
    for (int r = 0; r < 4; r++) {
        float inv = 1.f / lsum[r];
        int grow = q0 + ty*4 + r;
        float* orow = O + ((size_t)b*TQ + grow)*DMODEL + h*HDIM;
        *(float4*)(orow + tx*4) =
            make_float4(acc_o[r][0]*inv, acc_o[r][1]*inv, acc_o[r][2]*inv, acc_o[r][3]*inv);
        *(float4*)(orow + 64 + tx*4) =
            make_float4(acc_o[r][4]*inv, acc_o[r][5]*inv, acc_o[r][6]*inv, acc_o[r][7]*inv);
    }
}

// ---------------------------------------------------------------------------
// new_k / new_v permute:  out[b][i][j] = Kfull[b, (i&127)*16 + (j>>7), ((i>>7)<<7)|(j&127)]
// where Kfull = concat(cache, proj) along t. float4-vectorized over j.
// ---------------------------------------------------------------------------
__global__ void permute_kv(const float* __restrict__ cache,
                           const float* __restrict__ proj,
                           float* __restrict__ out)
{
    int idx = blockIdx.x * blockDim.x + threadIdx.x;   // float4 index
    // total float4 = 4*2048*512 = 4194304
    int j4  = idx & 511;
    int rem = idx >> 9;
    int i   = rem & 2047;
    int b   = rem >> 11;
    int j   = j4 << 2;
    int t   = (i & 127)*16 + (j >> 7);
    int c   = ((i >> 7) << 7) | (j & 127);
    const float* src = (t < CACHE)
        ? (cache + ((size_t)b*CACHE + t)*DMODEL + c)
        : (proj  + ((size_t)b*TQ + (t - CACHE))*DMODEL + c);
    ((float4*)out)[idx] = *(const float4*)src;
}

// ---------------------------------------------------------------------------
extern "C" void kernel_launch(void* const* d_in, const int* in_sizes, int n_in,
                              void* d_out, int out_size)
{
    const float* query  = (const float*)d_in[0];
    const float* key    = (const float*)d_in[1];
    const float* value  = (const float*)d_in[2];
    const float* cachek = (const float*)d_in[3];
    const float* cachev = (const float*)d_in[4];
    const float* Wq = (const float*)d_in[5];  const float* bq = (const float*)d_in[6];
    const float* Wk = (const float*)d_in[7];  const float* bk = (const float*)d_in[8];
    const float* Wv = (const float*)d_in[9];  const float* bv = (const float*)d_in[10];
    const float* Wo = (const float*)d_in[11]; const float* bo = (const float*)d_in[12];
    float* out = (float*)d_out;

    float *qp, *kp, *vp, *ap;
    cudaGetSymbolAddress((void**)&qp, g_qproj);
    cudaGetSymbolAddress((void**)&kp, g_kproj);
    cudaGetSymbolAddress((void**)&vp, g_vproj);
    cudaGetSymbolAddress((void**)&ap, g_attn);

    dim3 gemm_grid(2048/128, MROWS/128);   // (16, 32)
    sgemm_abt<<<gemm_grid, 256>>>(query, Wq, bq, qp);
    sgemm_abt<<<gemm_grid, 256>>>(key,   Wk, bk, kp);
    sgemm_abt<<<gemm_grid, 256>>>(value, Wv, bv, vp);

    size_t attn_smem = ATTN_SMEM_FLOATS * sizeof(float);   // 86016
    cudaFuncSetAttribute(attn_kernel, cudaFuncAttributeMaxDynamicSharedMemorySize,
                         (int)attn_smem);
    attn_kernel<<<dim3(TQ/64, BB*NHEADS), 256, attn_smem>>>(qp, cachek, cachev, ap);

    sgemm_abt<<<gemm_grid, 256>>>(ap, Wo, bo, out);

    permute_kv<<<4194304/256, 256>>>(cachek, kp, out + NEWK_OFF);
    permute_kv<<<4194304/256, 256>>>(cachev, vp, out + NEWV_OFF);
}

// round 4
// speedup vs baseline: 2.1218x; 2.1218x over previous
#include <cuda_runtime.h>
#include <cuda_bf16.h>
#include <math_constants.h>
#include <cstdint>

// Shapes
#define BB 4
#define TQ 1024
#define DMODEL 2048
#define NHEADS 16
#define HDIM 128
#define CACHE 1024
#define MROWS (BB*TQ)          // 4096
#define INV_SCALE 0.08838834764831843f  // 1/sqrt(128)

#define OUT_ELEMS   (BB*TQ*DMODEL)
#define NEWK_OFF    OUT_ELEMS
#define NEWV_OFF    (OUT_ELEMS + BB*2048*DMODEL)

__device__ float g_qproj[MROWS*DMODEL];
__device__ float g_kproj[MROWS*DMODEL];
__device__ float g_vproj[MROWS*DMODEL];
__device__ float g_attn [MROWS*DMODEL];

// ===========================================================================
// mma.sync tf32 GEMM: C[4096,2048] = A[4096,2048] @ W[2048,2048]^T + bias
// CTA 128x128, BK=32, 256 thr, warp grid 2(M)x4(N), warp tile 64x32.
// smem [row][k] stride 36 floats -> cp.async direct copy, conflict-free LDS.
// 4-stage cp.async pipeline.
// ===========================================================================
#define BK 32
#define STAGES 4
#define ROW_STRIDE 36                       // floats (32 data + 4 pad)
#define STAGE_FLOATS (256*ROW_STRIDE)       // A rows 0..127, B rows 128..255
#define STAGE_BYTES  (STAGE_FLOATS*4)       // 36864
#define GEMM_SMEM    (STAGES*STAGE_BYTES)   // 147456

__device__ __forceinline__ uint32_t smem_u32(const void* p) {
    uint32_t a;
    asm("{ .reg .u64 t; cvta.to.shared.u64 t, %1; cvt.u32.u64 %0, t; }"
        : "=r"(a) : "l"(p));
    return a;
}
__device__ __forceinline__ void cp_async16(uint32_t dst, const void* src) {
    asm volatile("cp.async.cg.shared.global [%0], [%1], 16;" :: "r"(dst), "l"(src));
}
#define CP_COMMIT() asm volatile("cp.async.commit_group;" ::: "memory")
#define CP_WAIT2()  asm volatile("cp.async.wait_group 2;" ::: "memory")

__device__ __forceinline__ uint32_t f2tf32(float f) {
    uint32_t r;
    asm("cvt.rna.tf32.f32 %0, %1;" : "=r"(r) : "f"(f));
    return r;
}
__device__ __forceinline__ void mma_tf32(float& d0, float& d1, float& d2, float& d3,
                                         uint32_t a0, uint32_t a1, uint32_t a2, uint32_t a3,
                                         uint32_t b0, uint32_t b1)
{
    asm volatile(
        "mma.sync.aligned.m16n8k8.row.col.f32.tf32.tf32.f32 "
        "{%0,%1,%2,%3}, {%4,%5,%6,%7}, {%8,%9}, {%0,%1,%2,%3};"
        : "+f"(d0), "+f"(d1), "+f"(d2), "+f"(d3)
        : "r"(a0), "r"(a1), "r"(a2), "r"(a3), "r"(b0), "r"(b1));
}

__global__ __launch_bounds__(256, 1)
void gemm_tf32(const float* __restrict__ A, const float* __restrict__ W,
               const float* __restrict__ bias, float* __restrict__ C)
{
    extern __shared__ __align__(128) float smem[];
    const uint32_t smem_addr = smem_u32(smem);
    const int tid  = threadIdx.x;
    const int wid  = tid >> 5;
    const int lane = tid & 31;
    const int bm = blockIdx.y * 128;
    const int bn = blockIdx.x * 128;
    const int wm = (wid & 1) * 64;       // warp M offset in tile
    const int wn = (wid >> 1) * 32;      // warp N offset in tile

    // ---- async stage loader: A rows 0..127, B(W) rows 128..255, [row][k] ----
    auto load_stage = [&](int it) {
        const int s  = it & (STAGES - 1);
        const int k0 = it * BK;
        const uint32_t sbase = smem_addr + s * STAGE_BYTES;
        const float* Ab = A + (size_t)bm * 2048 + k0;
        const float* Wb = W + (size_t)bn * 2048 + k0;
#pragma unroll
        for (int c = 0; c < 4; c++) {            // A: 1024 x 16B chunks
            int id = tid + c * 256;
            int row = id >> 3, seg = id & 7;
            cp_async16(sbase + row * (ROW_STRIDE*4) + seg * 16,
                       Ab + (size_t)row * 2048 + seg * 4);
        }
#pragma unroll
        for (int c = 0; c < 4; c++) {            // B: 1024 x 16B chunks
            int id = tid + c * 256;
            int row = id >> 3, seg = id & 7;
            cp_async16(sbase + (128 + row) * (ROW_STRIDE*4) + seg * 16,
                       Wb + (size_t)row * 2048 + seg * 4);
        }
    };

    float acc[4][4][4];
#pragma unroll
    for (int mf = 0; mf < 4; mf++)
#pragma unroll
        for (int nf = 0; nf < 4; nf++)
#pragma unroll
            for (int r = 0; r < 4; r++) acc[mf][nf][r] = 0.f;

    load_stage(0); CP_COMMIT();
    load_stage(1); CP_COMMIT();
    load_stage(2); CP_COMMIT();

    const int lr = lane >> 2;     // 0..7
    const int lc = lane & 3;      // 0..3

    for (int i = 0; i < 64; i++) {
        CP_WAIT2();               // stage i resident
        __syncthreads();          // all compute on buf (i-1)%4 done; data visible
        if (i + 3 < 64) load_stage(i + 3);
        CP_COMMIT();              // empty group near tail keeps counts uniform

        const float* As = smem + (size_t)(i & (STAGES-1)) * STAGE_FLOATS;
        const float* Bs = As + 128 * ROW_STRIDE;

#pragma unroll
        for (int ks = 0; ks < 4; ks++) {
            const int kb = ks * 8;
            // B fragments: b0 = B[k=lc][n=lr] -> Bs[wn+nf*8+lr][kb+lc]
            uint32_t bfr[4][2];
#pragma unroll
            for (int nf = 0; nf < 4; nf++) {
                const float* bp = Bs + (wn + nf*8 + lr) * ROW_STRIDE + kb + lc;
                bfr[nf][0] = f2tf32(bp[0]);
                bfr[nf][1] = f2tf32(bp[4]);
            }
#pragma unroll
            for (int mf = 0; mf < 4; mf++) {
                const float* ap0 = As + (wm + mf*16 + lr) * ROW_STRIDE + kb + lc;
                const float* ap1 = ap0 + 8 * ROW_STRIDE;
                uint32_t a0 = f2tf32(ap0[0]);
                uint32_t a1 = f2tf32(ap1[0]);
                uint32_t a2 = f2tf32(ap0[4]);
                uint32_t a3 = f2tf32(ap1[4]);
#pragma unroll
                for (int nf = 0; nf < 4; nf++)
                    mma_tf32(acc[mf][nf][0], acc[mf][nf][1],
                             acc[mf][nf][2], acc[mf][nf][3],
                             a0, a1, a2, a3, bfr[nf][0], bfr[nf][1]);
            }
        }
        __syncthreads();          // frag reads done before next overwrite
    }

    // ---- epilogue: bias + store (c0,c1 pairs are n-contiguous) ----
#pragma unroll
    for (int nf = 0; nf < 4; nf++) {
        const int col = bn + wn + nf*8 + lc*2;
        const float b0 = bias[col], b1 = bias[col + 1];
#pragma unroll
        for (int mf = 0; mf < 4; mf++) {
            const int row0 = bm + wm + mf*16 + lr;
            float2 v0 = make_float2(acc[mf][nf][0] + b0, acc[mf][nf][1] + b1);
            float2 v1 = make_float2(acc[mf][nf][2] + b0, acc[mf][nf][3] + b1);
            *(float2*)(C + (size_t)row0 * 2048 + col)        = v0;
            *(float2*)(C + (size_t)(row0 + 8) * 2048 + col)  = v1;
        }
    }
}

// ---------------------------------------------------------------------------
// Flash attention (fp32): causal over cache only. (unchanged)
// ---------------------------------------------------------------------------
#define QS_STRIDE 132
#define KT_STRIDE 68
#define PS_STRIDE 68
#define SMEM_Q   0
#define SMEM_KV  (64*QS_STRIDE)
#define SMEM_P   (SMEM_KV + 128*KT_STRIDE)
#define ATTN_SMEM_FLOATS (SMEM_P + 64*PS_STRIDE)

__global__ __launch_bounds__(256)
void attn_kernel(const float* __restrict__ Q,
                 const float* __restrict__ Kc,
                 const float* __restrict__ Vc,
                 float* __restrict__ O)
{
    extern __shared__ float sm[];
    float* Qs  = sm + SMEM_Q;
    float* Kts = sm + SMEM_KV;
    float* Vs  = sm + SMEM_KV;
    float* Ps  = sm + SMEM_P;

    const int tid = threadIdx.x;
    const int tx = tid & 15;
    const int ty = tid >> 4;
    const int qb = blockIdx.x;
    const int bh = blockIdx.y;
    const int b = bh >> 4, h = bh & 15;
    const int q0 = qb * 64;

    const float* Qbase = Q  + ((size_t)b*TQ    + q0)*DMODEL + h*HDIM;
    const float* Kbase = Kc + ((size_t)b*CACHE      )*DMODEL + h*HDIM;
    const float* Vbase = Vc + ((size_t)b*CACHE      )*DMODEL + h*HDIM;

#pragma unroll
    for (int q = 0; q < 8; q++) {
        int f = tid + 256*q;
        int row = f >> 5;
        int col = (f & 31) << 2;
        float4 v = *(const float4*)(Qbase + (size_t)row*DMODEL + col);
        *(float4*)&Qs[row*QS_STRIDE + col] = v;
    }
    __syncthreads();

    float m_old[4], lsum[4];
    float acc_o[4][8];
#pragma unroll
    for (int r = 0; r < 4; r++) {
        m_old[r] = -CUDART_INF_F; lsum[r] = 0.f;
#pragma unroll
        for (int c = 0; c < 8; c++) acc_o[r][c] = 0.f;
    }

    for (int kvb = 0; kvb <= qb; kvb++) {
        const int kv0 = kvb * 64;
#pragma unroll
        for (int q = 0; q < 8; q++) {
            int f = tid + 256*q;
            int row = f >> 5;
            int col = (f & 31) << 2;
            float4 v = *(const float4*)(Kbase + (size_t)(kv0+row)*DMODEL + col);
            Kts[(col+0)*KT_STRIDE + row] = v.x;
            Kts[(col+1)*KT_STRIDE + row] = v.y;
            Kts[(col+2)*KT_STRIDE + row] = v.z;
            Kts[(col+3)*KT_STRIDE + row] = v.w;
        }
        __syncthreads();

        float s[4][4];
#pragma unroll
        for (int r = 0; r < 4; r++)
#pragma unroll
            for (int c = 0; c < 4; c++) s[r][c] = 0.f;

#pragma unroll 8
        for (int d4 = 0; d4 < 32; d4++) {
            int d = d4 << 2;
            float4 a0 = *(const float4*)&Qs[(ty*4+0)*QS_STRIDE + d];
            float4 a1 = *(const float4*)&Qs[(ty*4+1)*QS_STRIDE + d];
            float4 a2 = *(const float4*)&Qs[(ty*4+2)*QS_STRIDE + d];
            float4 a3 = *(const float4*)&Qs[(ty*4+3)*QS_STRIDE + d];
            float4 b0 = *(const float4*)&Kts[(d+0)*KT_STRIDE + tx*4];
            float4 b1 = *(const float4*)&Kts[(d+1)*KT_STRIDE + tx*4];
            float4 b2 = *(const float4*)&Kts[(d+2)*KT_STRIDE + tx*4];
            float4 b3 = *(const float4*)&Kts[(d+3)*KT_STRIDE + tx*4];
            const float A0[4] = {a0.x,a0.y,a0.z,a0.w};
            const float A1[4] = {a1.x,a1.y,a1.z,a1.w};
            const float A2[4] = {a2.x,a2.y,a2.z,a2.w};
            const float A3[4] = {a3.x,a3.y,a3.z,a3.w};
            const float4 Bv[4] = {b0,b1,b2,b3};
#pragma unroll
            for (int i = 0; i < 4; i++) {
                s[0][0] += A0[i]*Bv[i].x; s[0][1] += A0[i]*Bv[i].y;
                s[0][2] += A0[i]*Bv[i].z; s[0][3] += A0[i]*Bv[i].w;
                s[1][0] += A1[i]*Bv[i].x; s[1][1] += A1[i]*Bv[i].y;
                s[1][2] += A1[i]*Bv[i].z; s[1][3] += A1[i]*Bv[i].w;
                s[2][0] += A2[i]*Bv[i].x; s[2][1] += A2[i]*Bv[i].y;
                s[2][2] += A2[i]*Bv[i].z; s[2][3] += A2[i]*Bv[i].w;
                s[3][0] += A3[i]*Bv[i].x; s[3][1] += A3[i]*Bv[i].y;
                s[3][2] += A3[i]*Bv[i].z; s[3][3] += A3[i]*Bv[i].w;
            }
        }

#pragma unroll
        for (int r = 0; r < 4; r++)
#pragma unroll
            for (int c = 0; c < 4; c++) s[r][c] *= INV_SCALE;
        if (kvb == qb) {
#pragma unroll
            for (int r = 0; r < 4; r++)
#pragma unroll
                for (int c = 0; c < 4; c++)
                    if (kv0 + tx*4 + c > q0 + ty*4 + r) s[r][c] = -1e30f;
        }

        float p[4][4];
#pragma unroll
        for (int r = 0; r < 4; r++) {
            float t = fmaxf(fmaxf(s[r][0], s[r][1]), fmaxf(s[r][2], s[r][3]));
#pragma unroll
            for (int off = 1; off < 16; off <<= 1)
                t = fmaxf(t, __shfl_xor_sync(0xffffffffu, t, off, 16));
            float mnew = fmaxf(m_old[r], t);
            float alpha = __expf(m_old[r] - mnew);
            float rs = 0.f;
#pragma unroll
            for (int c = 0; c < 4; c++) {
                p[r][c] = __expf(s[r][c] - mnew);
                rs += p[r][c];
            }
#pragma unroll
            for (int off = 1; off < 16; off <<= 1)
                rs += __shfl_xor_sync(0xffffffffu, rs, off, 16);
            lsum[r] = lsum[r]*alpha + rs;
#pragma unroll
            for (int c = 0; c < 8; c++) acc_o[r][c] *= alpha;
            m_old[r] = mnew;
            *(float4*)&Ps[(ty*4+r)*PS_STRIDE + tx*4] =
                make_float4(p[r][0], p[r][1], p[r][2], p[r][3]);
        }
        __syncthreads();

#pragma unroll
        for (int q = 0; q < 8; q++) {
            int f = tid + 256*q;
            int row = f >> 5;
            int col = (f & 31) << 2;
            float4 v = *(const float4*)(Vbase + (size_t)(kv0+row)*DMODEL + col);
            *(float4*)&Vs[row*QS_STRIDE + col] = v;
        }
        __syncthreads();

#pragma unroll 4
        for (int j = 0; j < 64; j++) {
            float pv0 = Ps[(ty*4+0)*PS_STRIDE + j];
            float pv1 = Ps[(ty*4+1)*PS_STRIDE + j];
            float pv2 = Ps[(ty*4+2)*PS_STRIDE + j];
            float pv3 = Ps[(ty*4+3)*PS_STRIDE + j];
            float4 v0 = *(const float4*)&Vs[j*QS_STRIDE + tx*4];
            float4 v1 = *(const float4*)&Vs[j*QS_STRIDE + 64 + tx*4];
            const float V8[8] = {v0.x,v0.y,v0.z,v0.w, v1.x,v1.y,v1.z,v1.w};
            const float PV[4] = {pv0,pv1,pv2,pv3};
#pragma unroll
            for (int r = 0; r < 4; r++)
#pragma unroll
                for (int c = 0; c < 8; c++)
                    acc_o[r][c] += PV[r]*V8[c];
        }
        __syncthreads();
    }

#pragma unroll
    for (int r = 0; r < 4; r++) {
        float inv = 1.f / lsum[r];
        int grow = q0 + ty*4 + r;
        float* orow = O + ((size_t)b*TQ + grow)*DMODEL + h*HDIM;
        *(float4*)(orow + tx*4) =
            make_float4(acc_o[r][0]*inv, acc_o[r][1]*inv, acc_o[r][2]*inv, acc_o[r][3]*inv);
        *(float4*)(orow + 64 + tx*4) =
            make_float4(acc_o[r][4]*inv, acc_o[r][5]*inv, acc_o[r][6]*inv, acc_o[r][7]*inv);
    }
}

// ---------------------------------------------------------------------------
// new_k / new_v permute (unchanged)
// ---------------------------------------------------------------------------
__global__ void permute_kv(const float* __restrict__ cache,
                           const float* __restrict__ proj,
                           float* __restrict__ out)
{
    int idx = blockIdx.x * blockDim.x + threadIdx.x;
    int j4  = idx & 511;
    int rem = idx >> 9;
    int i   = rem & 2047;
    int b   = rem >> 11;
    int j   = j4 << 2;
    int t   = (i & 127)*16 + (j >> 7);
    int c   = ((i >> 7) << 7) | (j & 127);
    const float* src = (t < CACHE)
        ? (cache + ((size_t)b*CACHE + t)*DMODEL + c)
        : (proj  + ((size_t)b*TQ + (t - CACHE))*DMODEL + c);
    ((float4*)out)[idx] = *(const float4*)src;
}

// ---------------------------------------------------------------------------
extern "C" void kernel_launch(void* const* d_in, const int* in_sizes, int n_in,
                              void* d_out, int out_size)
{
    const float* query  = (const float*)d_in[0];
    const float* key    = (const float*)d_in[1];
    const float* value  = (const float*)d_in[2];
    const float* cachek = (const float*)d_in[3];
    const float* cachev = (const float*)d_in[4];
    const float* Wq = (const float*)d_in[5];  const float* bq = (const float*)d_in[6];
    const float* Wk = (const float*)d_in[7];  const float* bk = (const float*)d_in[8];
    const float* Wv = (const float*)d_in[9];  const float* bv = (const float*)d_in[10];
    const float* Wo = (const float*)d_in[11]; const float* bo = (const float*)d_in[12];
    float* out = (float*)d_out;

    float *qp, *kp, *vp, *ap;
    cudaGetSymbolAddress((void**)&qp, g_qproj);
    cudaGetSymbolAddress((void**)&kp, g_kproj);
    cudaGetSymbolAddress((void**)&vp, g_vproj);
    cudaGetSymbolAddress((void**)&ap, g_attn);

    cudaFuncSetAttribute(gemm_tf32, cudaFuncAttributeMaxDynamicSharedMemorySize, GEMM_SMEM);
    dim3 ggrid(2048/128, MROWS/128);   // (16, 32)
    gemm_tf32<<<ggrid, 256, GEMM_SMEM>>>(query, Wq, bq, qp);
    gemm_tf32<<<ggrid, 256, GEMM_SMEM>>>(key,   Wk, bk, kp);
    gemm_tf32<<<ggrid, 256, GEMM_SMEM>>>(value, Wv, bv, vp);

    size_t attn_smem = ATTN_SMEM_FLOATS * sizeof(float);
    cudaFuncSetAttribute(attn_kernel, cudaFuncAttributeMaxDynamicSharedMemorySize,
                         (int)attn_smem);
    attn_kernel<<<dim3(TQ/64, BB*NHEADS), 256, attn_smem>>>(qp, cachek, cachev, ap);

    gemm_tf32<<<ggrid, 256, GEMM_SMEM>>>(ap, Wo, bo, out);

    permute_kv<<<4194304/256, 256>>>(cachek, kp, out + NEWK_OFF);
    permute_kv<<<4194304/256, 256>>>(cachev, vp, out + NEWV_OFF);
}

// round 6
// speedup vs baseline: 2.9389x; 1.3851x over previous
#include <cuda_runtime.h>
#include <cuda_bf16.h>
#include <math_constants.h>
#include <cstdint>

// Shapes
#define BB 4
#define TQ 1024
#define DMODEL 2048
#define NHEADS 16
#define HDIM 128
#define CACHE 1024
#define MROWS (BB*TQ)          // 4096
#define INV_SCALE 0.08838834764831843f  // 1/sqrt(128)

#define OUT_ELEMS   (BB*TQ*DMODEL)
#define NEWK_OFF    OUT_ELEMS
#define NEWV_OFF    (OUT_ELEMS + BB*2048*DMODEL)

// Scratch
__device__ float g_qproj[MROWS*DMODEL];
__device__ float g_kproj[MROWS*DMODEL];
__device__ float g_vproj[MROWS*DMODEL];
__device__ float g_attn [MROWS*DMODEL];
__device__ float g_qr   [MROWS*DMODEL];     // tf32-rounded inputs
__device__ float g_kr   [MROWS*DMODEL];
__device__ float g_vr   [MROWS*DMODEL];
__device__ float g_ckr  [BB*CACHE*DMODEL];  // tf32-rounded caches
__device__ float g_cvr  [BB*CACHE*DMODEL];
__device__ float g_wqr  [DMODEL*DMODEL];    // tf32-rounded weights
__device__ float g_wkr  [DMODEL*DMODEL];
__device__ float g_wvr  [DMODEL*DMODEL];
__device__ float g_wor  [DMODEL*DMODEL];

__device__ __forceinline__ uint32_t smem_u32(const void* p) {
    uint32_t a;
    asm("{ .reg .u64 t; cvta.to.shared.u64 t, %1; cvt.u32.u64 %0, t; }"
        : "=r"(a) : "l"(p));
    return a;
}
__device__ __forceinline__ void cp_async16(uint32_t dst, const void* src) {
    asm volatile("cp.async.cg.shared.global [%0], [%1], 16;" :: "r"(dst), "l"(src));
}
#define CP_COMMIT() asm volatile("cp.async.commit_group;" ::: "memory")
#define CP_WAIT2()  asm volatile("cp.async.wait_group 2;" ::: "memory")
#define CP_WAIT1()  asm volatile("cp.async.wait_group 1;" ::: "memory")

__device__ __forceinline__ uint32_t f2tf32(float f) {
    uint32_t r;
    asm("cvt.rna.tf32.f32 %0, %1;" : "=r"(r) : "f"(f));
    return r;
}
__device__ __forceinline__ float tf32f(float f) { return __uint_as_float(f2tf32(f)); }

__device__ __forceinline__ void mma_tf32(float& d0, float& d1, float& d2, float& d3,
                                         uint32_t a0, uint32_t a1, uint32_t a2, uint32_t a3,
                                         uint32_t b0, uint32_t b1)
{
    asm volatile(
        "mma.sync.aligned.m16n8k8.row.col.f32.tf32.tf32.f32 "
        "{%0,%1,%2,%3}, {%4,%5,%6,%7}, {%8,%9}, {%0,%1,%2,%3};"
        : "+f"(d0), "+f"(d1), "+f"(d2), "+f"(d3)
        : "r"(a0), "r"(a1), "r"(a2), "r"(a3), "r"(b0), "r"(b1));
}

// ===========================================================================
// prep: elementwise tf32 rounding (rna), float4 vectorized
// ===========================================================================
__global__ void round_tf32_kernel(const float* __restrict__ in, float* __restrict__ out)
{
    int idx = blockIdx.x * blockDim.x + threadIdx.x;
    float4 v = ((const float4*)in)[idx];
    v.x = tf32f(v.x); v.y = tf32f(v.y); v.z = tf32f(v.z); v.w = tf32f(v.w);
    ((float4*)out)[idx] = v;
}

// ===========================================================================
// mma.sync tf32 GEMM (operands pre-rounded -> no cvt in inner loop)
// C = A @ W^T ; epilogue: (C + bias) * scale, optional tf32 rounding
// ===========================================================================
#define BK 32
#define STAGES 4
#define ROW_STRIDE 36
#define STAGE_FLOATS (256*ROW_STRIDE)
#define STAGE_BYTES  (STAGE_FLOATS*4)
#define GEMM_SMEM    (STAGES*STAGE_BYTES)   // 147456

__global__ __launch_bounds__(256, 1)
void gemm_tf32(const float* __restrict__ A, const float* __restrict__ W,
               const float* __restrict__ bias, float* __restrict__ C,
               float scale, int round_out)
{
    extern __shared__ __align__(128) float smem[];
    const uint32_t smem_addr = smem_u32(smem);
    const int tid  = threadIdx.x;
    const int wid  = tid >> 5;
    const int lane = tid & 31;
    const int bm = blockIdx.y * 128;
    const int bn = blockIdx.x * 128;
    const int wm = (wid & 1) * 64;
    const int wn = (wid >> 1) * 32;

    auto load_stage = [&](int it) {
        const int s  = it & (STAGES - 1);
        const int k0 = it * BK;
        const uint32_t sbase = smem_addr + s * STAGE_BYTES;
        const float* Ab = A + (size_t)bm * 2048 + k0;
        const float* Wb = W + (size_t)bn * 2048 + k0;
#pragma unroll
        for (int c = 0; c < 4; c++) {
            int id = tid + c * 256;
            int row = id >> 3, seg = id & 7;
            cp_async16(sbase + row * (ROW_STRIDE*4) + seg * 16,
                       Ab + (size_t)row * 2048 + seg * 4);
        }
#pragma unroll
        for (int c = 0; c < 4; c++) {
            int id = tid + c * 256;
            int row = id >> 3, seg = id & 7;
            cp_async16(sbase + (128 + row) * (ROW_STRIDE*4) + seg * 16,
                       Wb + (size_t)row * 2048 + seg * 4);
        }
    };

    float acc[4][4][4];
#pragma unroll
    for (int mf = 0; mf < 4; mf++)
#pragma unroll
        for (int nf = 0; nf < 4; nf++)
#pragma unroll
            for (int r = 0; r < 4; r++) acc[mf][nf][r] = 0.f;

    load_stage(0); CP_COMMIT();
    load_stage(1); CP_COMMIT();
    load_stage(2); CP_COMMIT();

    const int lr = lane >> 2;
    const int lc = lane & 3;

    for (int i = 0; i < 64; i++) {
        CP_WAIT2();
        __syncthreads();
        if (i + 3 < 64) load_stage(i + 3);
        CP_COMMIT();

        const float* As = smem + (size_t)(i & (STAGES-1)) * STAGE_FLOATS;
        const float* Bs = As + 128 * ROW_STRIDE;

#pragma unroll
        for (int ks = 0; ks < 4; ks++) {
            const int kb = ks * 8;
            uint32_t bfr[4][2];
#pragma unroll
            for (int nf = 0; nf < 4; nf++) {
                const float* bp = Bs + (wn + nf*8 + lr) * ROW_STRIDE + kb + lc;
                bfr[nf][0] = __float_as_uint(bp[0]);
                bfr[nf][1] = __float_as_uint(bp[4]);
            }
#pragma unroll
            for (int mf = 0; mf < 4; mf++) {
                const float* ap0 = As + (wm + mf*16 + lr) * ROW_STRIDE + kb + lc;
                const float* ap1 = ap0 + 8 * ROW_STRIDE;
                uint32_t a0 = __float_as_uint(ap0[0]);
                uint32_t a1 = __float_as_uint(ap1[0]);
                uint32_t a2 = __float_as_uint(ap0[4]);
                uint32_t a3 = __float_as_uint(ap1[4]);
#pragma unroll
                for (int nf = 0; nf < 4; nf++)
                    mma_tf32(acc[mf][nf][0], acc[mf][nf][1],
                             acc[mf][nf][2], acc[mf][nf][3],
                             a0, a1, a2, a3, bfr[nf][0], bfr[nf][1]);
            }
        }
        __syncthreads();
    }

#pragma unroll
    for (int nf = 0; nf < 4; nf++) {
        const int col = bn + wn + nf*8 + lc*2;
        const float b0 = bias[col], b1 = bias[col + 1];
#pragma unroll
        for (int mf = 0; mf < 4; mf++) {
            const int row0 = bm + wm + mf*16 + lr;
            float v0 = (acc[mf][nf][0] + b0) * scale;
            float v1 = (acc[mf][nf][1] + b1) * scale;
            float v2 = (acc[mf][nf][2] + b0) * scale;
            float v3 = (acc[mf][nf][3] + b1) * scale;
            if (round_out) { v0 = tf32f(v0); v1 = tf32f(v1); v2 = tf32f(v2); v3 = tf32f(v3); }
            *(float2*)(C + (size_t)row0 * 2048 + col)       = make_float2(v0, v1);
            *(float2*)(C + (size_t)(row0 + 8) * 2048 + col) = make_float2(v2, v3);
        }
    }
}

// ===========================================================================
// Tensor-core flash attention (tf32 mma), causal over cache only.
// BQ=64, BKV=64, 128 threads (4 warps), warp tile 16 q-rows x full tile.
// Q pre-scaled (1/sqrt(dh)) + pre-rounded; K/V caches pre-rounded (tf32).
// Output rounded to tf32 (feeds O-projection GEMM).
// ===========================================================================
#define AQ_STRIDE 132
#define AK_STRIDE 132
#define AV_STRIDE 136
#define AP_STRIDE 68
#define AQS 0
#define AKS (64*AQ_STRIDE)              // 8448
#define AVS (AKS + 2*64*AK_STRIDE)      // 25344
#define APS (AVS + 2*64*AV_STRIDE)      // 42752
#define ATTN_FLOATS (APS + 64*AP_STRIDE)// 47104 -> 188416 B

__global__ __launch_bounds__(128, 1)
void attn_mma(const float* __restrict__ Q,
              const float* __restrict__ K,
              const float* __restrict__ V,
              float* __restrict__ O)
{
    extern __shared__ __align__(128) float sm[];
    const uint32_t smaddr = smem_u32(sm);
    const int tid = threadIdx.x;
    const int w = tid >> 5, lane = tid & 31;
    const int lr = lane >> 2, lc = lane & 3;
    const int qb = gridDim.x - 1 - blockIdx.x;   // big tiles first
    const int bh = blockIdx.y;
    const int b = bh >> 4, h = bh & 15;
    const int q0 = qb * 64;
    const int nt = qb + 1;

    const float* Qg = Q + ((size_t)b*TQ + q0)*DMODEL + h*HDIM;
    const float* Kg = K + (size_t)b*CACHE*DMODEL + h*HDIM;
    const float* Vg = V + (size_t)b*CACHE*DMODEL + h*HDIM;

    // Q tile -> smem (already tf32+scaled; plain copy)
#pragma unroll
    for (int c = 0; c < 16; c++) {
        int id = tid + c*128;
        int row = id >> 5, c4 = (id & 31) << 2;
        float4 v = *(const float4*)(Qg + (size_t)row*2048 + c4);
        *(float4*)&sm[AQS + row*AQ_STRIDE + c4] = v;
    }

    auto load_kv = [&](int it) {
        const int s = it & 1;
        const int kv0 = it * 64;
        const uint32_t kd = smaddr + (AKS + s*64*AK_STRIDE)*4;
        const uint32_t vd = smaddr + (AVS + s*64*AV_STRIDE)*4;
        const float* Kt = Kg + (size_t)kv0*2048;
        const float* Vt = Vg + (size_t)kv0*2048;
#pragma unroll
        for (int c = 0; c < 16; c++) {
            int id = tid + c*128;
            int row = id >> 5, seg = id & 31;
            cp_async16(kd + row*(AK_STRIDE*4) + seg*16, Kt + (size_t)row*2048 + seg*4);
        }
#pragma unroll
        for (int c = 0; c < 16; c++) {
            int id = tid + c*128;
            int row = id >> 5, seg = id & 31;
            cp_async16(vd + row*(AV_STRIDE*4) + seg*16, Vt + (size_t)row*2048 + seg*4);
        }
    };

    load_kv(0); CP_COMMIT();

    float m0 = -1e30f, m1 = -1e30f, l0 = 0.f, l1 = 0.f;
    float oacc[16][4];
#pragma unroll
    for (int nf = 0; nf < 16; nf++)
#pragma unroll
        for (int r = 0; r < 4; r++) oacc[nf][r] = 0.f;

    const int qrow0 = q0 + w*16 + lr;      // global q row (and +8)

    for (int i = 0; i < nt; i++) {
        if (i + 1 < nt) load_kv(i + 1);
        CP_COMMIT();
        CP_WAIT1();
        __syncthreads();

        // ---- S = Q K^T (pre-scaled) ----
        const float* Kb = sm + AKS + (i & 1)*64*AK_STRIDE;
        const float* Qw = sm + AQS + w*16*AQ_STRIDE;
        float sacc[8][4];
#pragma unroll
        for (int nf = 0; nf < 8; nf++)
#pragma unroll
            for (int r = 0; r < 4; r++) sacc[nf][r] = 0.f;

#pragma unroll
        for (int kb = 0; kb < 16; kb++) {
            const float* ap = Qw + lr*AQ_STRIDE + kb*8 + lc;
            uint32_t a0 = __float_as_uint(ap[0]);
            uint32_t a1 = __float_as_uint(ap[8*AQ_STRIDE]);
            uint32_t a2 = __float_as_uint(ap[4]);
            uint32_t a3 = __float_as_uint(ap[8*AQ_STRIDE + 4]);
#pragma unroll
            for (int nf = 0; nf < 8; nf++) {
                const float* bp = Kb + (nf*8 + lr)*AK_STRIDE + kb*8 + lc;
                mma_tf32(sacc[nf][0], sacc[nf][1], sacc[nf][2], sacc[nf][3],
                         a0, a1, a2, a3,
                         __float_as_uint(bp[0]), __float_as_uint(bp[4]));
            }
        }

        // ---- causal mask (diag tile only) ----
        const int kvb = i*64;
        if (i == qb) {
#pragma unroll
            for (int nf = 0; nf < 8; nf++) {
                int col = kvb + nf*8 + 2*lc;
                if (col     > qrow0)     sacc[nf][0] = -1e30f;
                if (col + 1 > qrow0)     sacc[nf][1] = -1e30f;
                if (col     > qrow0 + 8) sacc[nf][2] = -1e30f;
                if (col + 1 > qrow0 + 8) sacc[nf][3] = -1e30f;
            }
        }

        // ---- online softmax ----
        float mx0 = -1e30f, mx1 = -1e30f;
#pragma unroll
        for (int nf = 0; nf < 8; nf++) {
            mx0 = fmaxf(mx0, fmaxf(sacc[nf][0], sacc[nf][1]));
            mx1 = fmaxf(mx1, fmaxf(sacc[nf][2], sacc[nf][3]));
        }
        mx0 = fmaxf(mx0, __shfl_xor_sync(0xffffffffu, mx0, 1));
        mx0 = fmaxf(mx0, __shfl_xor_sync(0xffffffffu, mx0, 2));
        mx1 = fmaxf(mx1, __shfl_xor_sync(0xffffffffu, mx1, 1));
        mx1 = fmaxf(mx1, __shfl_xor_sync(0xffffffffu, mx1, 2));
        float mn0 = fmaxf(m0, mx0), mn1 = fmaxf(m1, mx1);
        float al0 = __expf(m0 - mn0), al1 = __expf(m1 - mn1);
        m0 = mn0; m1 = mn1;

        float* Pw = sm + APS + (w*16)*AP_STRIDE;
        float rs0 = 0.f, rs1 = 0.f;
#pragma unroll
        for (int nf = 0; nf < 8; nf++) {
            float p0 = __expf(sacc[nf][0] - mn0);
            float p1 = __expf(sacc[nf][1] - mn0);
            float p2 = __expf(sacc[nf][2] - mn1);
            float p3 = __expf(sacc[nf][3] - mn1);
            rs0 += p0 + p1; rs1 += p2 + p3;
            *(float2*)&Pw[lr*AP_STRIDE + nf*8 + 2*lc]     = make_float2(tf32f(p0), tf32f(p1));
            *(float2*)&Pw[(lr+8)*AP_STRIDE + nf*8 + 2*lc] = make_float2(tf32f(p2), tf32f(p3));
        }
        rs0 += __shfl_xor_sync(0xffffffffu, rs0, 1);
        rs0 += __shfl_xor_sync(0xffffffffu, rs0, 2);
        rs1 += __shfl_xor_sync(0xffffffffu, rs1, 1);
        rs1 += __shfl_xor_sync(0xffffffffu, rs1, 2);
        l0 = l0*al0 + rs0; l1 = l1*al1 + rs1;
#pragma unroll
        for (int nf = 0; nf < 16; nf++) {
            oacc[nf][0] *= al0; oacc[nf][1] *= al0;
            oacc[nf][2] *= al1; oacc[nf][3] *= al1;
        }
        __syncwarp();

        // ---- O += P @ V ----
        const float* Vb = sm + AVS + (i & 1)*64*AV_STRIDE;
#pragma unroll
        for (int kb = 0; kb < 8; kb++) {
            const float* ap = Pw + lr*AP_STRIDE + kb*8 + lc;
            uint32_t a0 = __float_as_uint(ap[0]);
            uint32_t a1 = __float_as_uint(ap[8*AP_STRIDE]);
            uint32_t a2 = __float_as_uint(ap[4]);
            uint32_t a3 = __float_as_uint(ap[8*AP_STRIDE + 4]);
#pragma unroll
            for (int nf = 0; nf < 16; nf++) {
                const float* bp = Vb + (kb*8 + lc)*AV_STRIDE + nf*8 + lr;
                mma_tf32(oacc[nf][0], oacc[nf][1], oacc[nf][2], oacc[nf][3],
                         a0, a1, a2, a3,
                         __float_as_uint(bp[0]), __float_as_uint(bp[4*AV_STRIDE]));
            }
        }
        __syncthreads();   // K/V/P reads done before next prefetch overwrites
    }

    // ---- finalize: /lsum, round to tf32 (feeds O-proj), store ----
    float inv0 = 1.f / l0, inv1 = 1.f / l1;
    float* Ob = O + ((size_t)b*TQ + q0 + w*16)*DMODEL + h*HDIM;
#pragma unroll
    for (int nf = 0; nf < 16; nf++) {
        int col = nf*8 + 2*lc;
        *(float2*)(Ob + (size_t)lr*2048 + col) =
            make_float2(tf32f(oacc[nf][0]*inv0), tf32f(oacc[nf][1]*inv0));
        *(float2*)(Ob + (size_t)(lr+8)*2048 + col) =
            make_float2(tf32f(oacc[nf][2]*inv1), tf32f(oacc[nf][3]*inv1));
    }
}

// ---------------------------------------------------------------------------
// new_k / new_v permute (unchanged)
// ---------------------------------------------------------------------------
__global__ void permute_kv(const float* __restrict__ cache,
                           const float* __restrict__ proj,
                           float* __restrict__ out)
{
    int idx = blockIdx.x * blockDim.x + threadIdx.x;
    int j4  = idx & 511;
    int rem = idx >> 9;
    int i   = rem & 2047;
    int b   = rem >> 11;
    int j   = j4 << 2;
    int t   = (i & 127)*16 + (j >> 7);
    int c   = ((i >> 7) << 7) | (j & 127);
    const float* src = (t < CACHE)
        ? (cache + ((size_t)b*CACHE + t)*DMODEL + c)
        : (proj  + ((size_t)b*TQ + (t - CACHE))*DMODEL + c);
    ((float4*)out)[idx] = *(const float4*)src;
}

// ---------------------------------------------------------------------------
extern "C" void kernel_launch(void* const* d_in, const int* in_sizes, int n_in,
                              void* d_out, int out_size)
{
    const float* query  = (const float*)d_in[0];
    const float* key    = (const float*)d_in[1];
    const float* value  = (const float*)d_in[2];
    const float* cachek = (const float*)d_in[3];
    const float* cachev = (const float*)d_in[4];
    const float* Wq = (const float*)d_in[5];  const float* bq = (const float*)d_in[6];
    const float* Wk = (const float*)d_in[7];  const float* bk = (const float*)d_in[8];
    const float* Wv = (const float*)d_in[9];  const float* bv = (const float*)d_in[10];
    const float* Wo = (const float*)d_in[11]; const float* bo = (const float*)d_in[12];
    float* out = (float*)d_out;

    float *qp, *kp, *vp, *ap, *qr, *kr, *vr, *ckr, *cvr, *wqr, *wkr, *wvr, *wor;
    cudaGetSymbolAddress((void**)&qp,  g_qproj);
    cudaGetSymbolAddress((void**)&kp,  g_kproj);
    cudaGetSymbolAddress((void**)&vp,  g_vproj);
    cudaGetSymbolAddress((void**)&ap,  g_attn);
    cudaGetSymbolAddress((void**)&qr,  g_qr);
    cudaGetSymbolAddress((void**)&kr,  g_kr);
    cudaGetSymbolAddress((void**)&vr,  g_vr);
    cudaGetSymbolAddress((void**)&ckr, g_ckr);
    cudaGetSymbolAddress((void**)&cvr, g_cvr);
    cudaGetSymbolAddress((void**)&wqr, g_wqr);
    cudaGetSymbolAddress((void**)&wkr, g_wkr);
    cudaGetSymbolAddress((void**)&wvr, g_wvr);
    cudaGetSymbolAddress((void**)&wor, g_wor);

    // prep: tf32-round operands (float4 grids)
    const int ACT4 = MROWS*DMODEL/4;        // 2097152
    const int W4   = DMODEL*DMODEL/4;       // 1048576
    round_tf32_kernel<<<ACT4/256, 256>>>(query,  qr);
    round_tf32_kernel<<<ACT4/256, 256>>>(key,    kr);
    round_tf32_kernel<<<ACT4/256, 256>>>(value,  vr);
    round_tf32_kernel<<<ACT4/256, 256>>>(cachek, ckr);
    round_tf32_kernel<<<ACT4/256, 256>>>(cachev, cvr);
    round_tf32_kernel<<<W4/256, 256>>>(Wq, wqr);
    round_tf32_kernel<<<W4/256, 256>>>(Wk, wkr);
    round_tf32_kernel<<<W4/256, 256>>>(Wv, wvr);
    round_tf32_kernel<<<W4/256, 256>>>(Wo, wor);

    cudaFuncSetAttribute(gemm_tf32, cudaFuncAttributeMaxDynamicSharedMemorySize, GEMM_SMEM);
    dim3 ggrid(2048/128, MROWS/128);   // (16, 32)
    // Q projection: fold 1/sqrt(dh) + round output (feeds attention only)
    gemm_tf32<<<ggrid, 256, GEMM_SMEM>>>(qr, wqr, bq, qp, INV_SCALE, 1);
    gemm_tf32<<<ggrid, 256, GEMM_SMEM>>>(kr, wkr, bk, kp, 1.f, 0);
    gemm_tf32<<<ggrid, 256, GEMM_SMEM>>>(vr, wvr, bv, vp, 1.f, 0);

    cudaFuncSetAttribute(attn_mma, cudaFuncAttributeMaxDynamicSharedMemorySize,
                         ATTN_FLOATS*4);
    attn_mma<<<dim3(TQ/64, BB*NHEADS), 128, ATTN_FLOATS*4>>>(qp, ckr, cvr, ap);

    gemm_tf32<<<ggrid, 256, GEMM_SMEM>>>(ap, wor, bo, out, 1.f, 0);

    permute_kv<<<4194304/256, 256>>>(cachek, kp, out + NEWK_OFF);
    permute_kv<<<4194304/256, 256>>>(cachev, vp, out + NEWV_OFF);
}

// round 7
// speedup vs baseline: 3.1013x; 1.0553x over previous
#include <cuda_runtime.h>
#include <cuda_bf16.h>
#include <math_constants.h>
#include <cstdint>

// Shapes
#define BB 4
#define TQ 1024
#define DMODEL 2048
#define NHEADS 16
#define HDIM 128
#define CACHE 1024
#define MROWS (BB*TQ)          // 4096
#define INV_SCALE 0.08838834764831843f  // 1/sqrt(128)

#define OUT_ELEMS   (BB*TQ*DMODEL)
#define NEWK_OFF    OUT_ELEMS
#define NEWV_OFF    (OUT_ELEMS + BB*2048*DMODEL)

// Scratch
__device__ float g_qproj[MROWS*DMODEL];
__device__ float g_kproj[MROWS*DMODEL];
__device__ float g_vproj[MROWS*DMODEL];
__device__ float g_attn [MROWS*DMODEL];
__device__ float g_qr   [MROWS*DMODEL];
__device__ float g_kr   [MROWS*DMODEL];
__device__ float g_vr   [MROWS*DMODEL];
__device__ float g_ckr  [BB*CACHE*DMODEL];
__device__ float g_cvr  [BB*CACHE*DMODEL];
__device__ float g_wqr  [DMODEL*DMODEL];
__device__ float g_wkr  [DMODEL*DMODEL];
__device__ float g_wvr  [DMODEL*DMODEL];
__device__ float g_wor  [DMODEL*DMODEL];

__device__ __forceinline__ uint32_t smem_u32(const void* p) {
    uint32_t a;
    asm("{ .reg .u64 t; cvta.to.shared.u64 t, %1; cvt.u32.u64 %0, t; }"
        : "=r"(a) : "l"(p));
    return a;
}
__device__ __forceinline__ void cp_async16(uint32_t dst, const void* src) {
    asm volatile("cp.async.cg.shared.global [%0], [%1], 16;" :: "r"(dst), "l"(src));
}
#define CP_COMMIT() asm volatile("cp.async.commit_group;" ::: "memory")
#define CP_WAIT2()  asm volatile("cp.async.wait_group 2;" ::: "memory")
#define CP_WAIT0()  asm volatile("cp.async.wait_group 0;" ::: "memory")

__device__ __forceinline__ uint32_t f2tf32(float f) {
    uint32_t r;
    asm("cvt.rna.tf32.f32 %0, %1;" : "=r"(r) : "f"(f));
    return r;
}
__device__ __forceinline__ float tf32f(float f) { return __uint_as_float(f2tf32(f)); }

__device__ __forceinline__ void mma_tf32(float& d0, float& d1, float& d2, float& d3,
                                         uint32_t a0, uint32_t a1, uint32_t a2, uint32_t a3,
                                         uint32_t b0, uint32_t b1)
{
    asm volatile(
        "mma.sync.aligned.m16n8k8.row.col.f32.tf32.tf32.f32 "
        "{%0,%1,%2,%3}, {%4,%5,%6,%7}, {%8,%9}, {%0,%1,%2,%3};"
        : "+f"(d0), "+f"(d1), "+f"(d2), "+f"(d3)
        : "r"(a0), "r"(a1), "r"(a2), "r"(a3), "r"(b0), "r"(b1));
}

// ===========================================================================
// prep: elementwise tf32 rounding (rna), float4 vectorized, multi-array
// ===========================================================================
__global__ void round5_kernel(const float* i0, float* o0, const float* i1, float* o1,
                              const float* i2, float* o2, const float* i3, float* o3,
                              const float* i4, float* o4)
{
    int idx = blockIdx.x * blockDim.x + threadIdx.x;
    const float* in; float* out;
    switch (blockIdx.y) {
        case 0: in = i0; out = o0; break;
        case 1: in = i1; out = o1; break;
        case 2: in = i2; out = o2; break;
        case 3: in = i3; out = o3; break;
        default: in = i4; out = o4; break;
    }
    float4 v = ((const float4*)in)[idx];
    v.x = tf32f(v.x); v.y = tf32f(v.y); v.z = tf32f(v.z); v.w = tf32f(v.w);
    ((float4*)out)[idx] = v;
}
__global__ void round4_kernel(const float* i0, float* o0, const float* i1, float* o1,
                              const float* i2, float* o2, const float* i3, float* o3)
{
    int idx = blockIdx.x * blockDim.x + threadIdx.x;
    const float* in; float* out;
    switch (blockIdx.y) {
        case 0: in = i0; out = o0; break;
        case 1: in = i1; out = o1; break;
        case 2: in = i2; out = o2; break;
        default: in = i3; out = o3; break;
    }
    float4 v = ((const float4*)in)[idx];
    v.x = tf32f(v.x); v.y = tf32f(v.y); v.z = tf32f(v.z); v.w = tf32f(v.w);
    ((float4*)out)[idx] = v;
}

// ===========================================================================
// mma.sync tf32 GEMM, single barrier per k-iter. grid.z selects operand set
// (merged QKV). z-set 0 applies scale + tf32 output rounding (Q path).
// ===========================================================================
#define BK 32
#define STAGES 4
#define ROW_STRIDE 36
#define STAGE_FLOATS (256*ROW_STRIDE)
#define STAGE_BYTES  (STAGE_FLOATS*4)
#define GEMM_SMEM    (STAGES*STAGE_BYTES)   // 147456

struct GemmSet { const float *A, *W, *bias; float *C; float scale; int round_out; };

__global__ __launch_bounds__(256, 1)
void gemm_tf32(GemmSet s0, GemmSet s1, GemmSet s2)
{
    const GemmSet& S = (blockIdx.z == 0) ? s0 : (blockIdx.z == 1) ? s1 : s2;
    const float* __restrict__ A = S.A;
    const float* __restrict__ W = S.W;
    const float* __restrict__ bias = S.bias;
    float* __restrict__ C = S.C;

    extern __shared__ __align__(128) float smem[];
    const uint32_t smem_addr = smem_u32(smem);
    const int tid  = threadIdx.x;
    const int wid  = tid >> 5;
    const int lane = tid & 31;
    const int bm = blockIdx.y * 128;
    const int bn = blockIdx.x * 128;
    const int wm = (wid & 1) * 64;
    const int wn = (wid >> 1) * 32;

    auto load_stage = [&](int it) {
        const int s  = it & (STAGES - 1);
        const int k0 = it * BK;
        const uint32_t sbase = smem_addr + s * STAGE_BYTES;
        const float* Ab = A + (size_t)bm * 2048 + k0;
        const float* Wb = W + (size_t)bn * 2048 + k0;
#pragma unroll
        for (int c = 0; c < 4; c++) {
            int id = tid + c * 256;
            int row = id >> 3, seg = id & 7;
            cp_async16(sbase + row * (ROW_STRIDE*4) + seg * 16,
                       Ab + (size_t)row * 2048 + seg * 4);
        }
#pragma unroll
        for (int c = 0; c < 4; c++) {
            int id = tid + c * 256;
            int row = id >> 3, seg = id & 7;
            cp_async16(sbase + (128 + row) * (ROW_STRIDE*4) + seg * 16,
                       Wb + (size_t)row * 2048 + seg * 4);
        }
    };

    float acc[4][4][4];
#pragma unroll
    for (int mf = 0; mf < 4; mf++)
#pragma unroll
        for (int nf = 0; nf < 4; nf++)
#pragma unroll
            for (int r = 0; r < 4; r++) acc[mf][nf][r] = 0.f;

    load_stage(0); CP_COMMIT();
    load_stage(1); CP_COMMIT();
    load_stage(2); CP_COMMIT();

    const int lr = lane >> 2;
    const int lc = lane & 3;

    for (int i = 0; i < 64; i++) {
        CP_WAIT2();               // stage i resident
        __syncthreads();          // everyone done reading buf (i-1)&3
        if (i + 3 < 64) load_stage(i + 3);   // writes buf (i-1)&3 — safe now
        CP_COMMIT();

        const float* As = smem + (size_t)(i & (STAGES-1)) * STAGE_FLOATS;
        const float* Bs = As + 128 * ROW_STRIDE;

#pragma unroll
        for (int ks = 0; ks < 4; ks++) {
            const int kb = ks * 8;
            uint32_t bfr[4][2];
#pragma unroll
            for (int nf = 0; nf < 4; nf++) {
                const float* bp = Bs + (wn + nf*8 + lr) * ROW_STRIDE + kb + lc;
                bfr[nf][0] = __float_as_uint(bp[0]);
                bfr[nf][1] = __float_as_uint(bp[4]);
            }
#pragma unroll
            for (int mf = 0; mf < 4; mf++) {
                const float* ap0 = As + (wm + mf*16 + lr) * ROW_STRIDE + kb + lc;
                const float* ap1 = ap0 + 8 * ROW_STRIDE;
                uint32_t a0 = __float_as_uint(ap0[0]);
                uint32_t a1 = __float_as_uint(ap1[0]);
                uint32_t a2 = __float_as_uint(ap0[4]);
                uint32_t a3 = __float_as_uint(ap1[4]);
#pragma unroll
                for (int nf = 0; nf < 4; nf++)
                    mma_tf32(acc[mf][nf][0], acc[mf][nf][1],
                             acc[mf][nf][2], acc[mf][nf][3],
                             a0, a1, a2, a3, bfr[nf][0], bfr[nf][1]);
            }
        }
        // no trailing barrier: next iter's leading barrier protects buffer reuse
    }

    const float scale = S.scale;
    const int round_out = S.round_out;
#pragma unroll
    for (int nf = 0; nf < 4; nf++) {
        const int col = bn + wn + nf*8 + lc*2;
        const float b0 = bias[col], b1 = bias[col + 1];
#pragma unroll
        for (int mf = 0; mf < 4; mf++) {
            const int row0 = bm + wm + mf*16 + lr;
            float v0 = (acc[mf][nf][0] + b0) * scale;
            float v1 = (acc[mf][nf][1] + b1) * scale;
            float v2 = (acc[mf][nf][2] + b0) * scale;
            float v3 = (acc[mf][nf][3] + b1) * scale;
            if (round_out) { v0 = tf32f(v0); v1 = tf32f(v1); v2 = tf32f(v2); v3 = tf32f(v3); }
            *(float2*)(C + (size_t)row0 * 2048 + col)       = make_float2(v0, v1);
            *(float2*)(C + (size_t)(row0 + 8) * 2048 + col) = make_float2(v2, v3);
        }
    }
}

// ===========================================================================
// Tensor-core flash attention (tf32 mma), causal over cache only.
// Single barrier per kv-iter: wait_group 0 -> barrier -> prefetch -> compute.
// ===========================================================================
#define AQ_STRIDE 132
#define AK_STRIDE 132
#define AV_STRIDE 136
#define AP_STRIDE 68
#define AQS 0
#define AKS (64*AQ_STRIDE)
#define AVS (AKS + 2*64*AK_STRIDE)
#define APS (AVS + 2*64*AV_STRIDE)
#define ATTN_FLOATS (APS + 64*AP_STRIDE)   // 47104 floats -> 188416 B

__global__ __launch_bounds__(128, 1)
void attn_mma(const float* __restrict__ Q,
              const float* __restrict__ K,
              const float* __restrict__ V,
              float* __restrict__ O)
{
    extern __shared__ __align__(128) float sm[];
    const uint32_t smaddr = smem_u32(sm);
    const int tid = threadIdx.x;
    const int w = tid >> 5, lane = tid & 31;
    const int lr = lane >> 2, lc = lane & 3;
    const int qb = gridDim.x - 1 - blockIdx.x;   // big tiles first
    const int bh = blockIdx.y;
    const int b = bh >> 4, h = bh & 15;
    const int q0 = qb * 64;
    const int nt = qb + 1;

    const float* Qg = Q + ((size_t)b*TQ + q0)*DMODEL + h*HDIM;
    const float* Kg = K + (size_t)b*CACHE*DMODEL + h*HDIM;
    const float* Vg = V + (size_t)b*CACHE*DMODEL + h*HDIM;

#pragma unroll
    for (int c = 0; c < 16; c++) {
        int id = tid + c*128;
        int row = id >> 5, c4 = (id & 31) << 2;
        float4 v = *(const float4*)(Qg + (size_t)row*2048 + c4);
        *(float4*)&sm[AQS + row*AQ_STRIDE + c4] = v;
    }

    auto load_kv = [&](int it) {
        const int s = it & 1;
        const int kv0 = it * 64;
        const uint32_t kd = smaddr + (AKS + s*64*AK_STRIDE)*4;
        const uint32_t vd = smaddr + (AVS + s*64*AV_STRIDE)*4;
        const float* Kt = Kg + (size_t)kv0*2048;
        const float* Vt = Vg + (size_t)kv0*2048;
#pragma unroll
        for (int c = 0; c < 16; c++) {
            int id = tid + c*128;
            int row = id >> 5, seg = id & 31;
            cp_async16(kd + row*(AK_STRIDE*4) + seg*16, Kt + (size_t)row*2048 + seg*4);
        }
#pragma unroll
        for (int c = 0; c < 16; c++) {
            int id = tid + c*128;
            int row = id >> 5, seg = id & 31;
            cp_async16(vd + row*(AV_STRIDE*4) + seg*16, Vt + (size_t)row*2048 + seg*4);
        }
    };

    load_kv(0); CP_COMMIT();

    float m0 = -1e30f, m1 = -1e30f, l0 = 0.f, l1 = 0.f;
    float oacc[16][4];
#pragma unroll
    for (int nf = 0; nf < 16; nf++)
#pragma unroll
        for (int r = 0; r < 4; r++) oacc[nf][r] = 0.f;

    const int qrow0 = q0 + w*16 + lr;

    for (int i = 0; i < nt; i++) {
        CP_WAIT0();               // buf i&1 resident (only load(i) outstanding)
        __syncthreads();          // everyone done reading buf (i-1)&1
        if (i + 1 < nt) { load_kv(i + 1); CP_COMMIT(); }   // writes buf (i+1)&1=(i-1)&1

        // ---- S = Q K^T (pre-scaled) ----
        const float* Kb = sm + AKS + (i & 1)*64*AK_STRIDE;
        const float* Qw = sm + AQS + w*16*AQ_STRIDE;
        float sacc[8][4];
#pragma unroll
        for (int nf = 0; nf < 8; nf++)
#pragma unroll
            for (int r = 0; r < 4; r++) sacc[nf][r] = 0.f;

#pragma unroll
        for (int kb = 0; kb < 16; kb++) {
            const float* ap = Qw + lr*AQ_STRIDE + kb*8 + lc;
            uint32_t a0 = __float_as_uint(ap[0]);
            uint32_t a1 = __float_as_uint(ap[8*AQ_STRIDE]);
            uint32_t a2 = __float_as_uint(ap[4]);
            uint32_t a3 = __float_as_uint(ap[8*AQ_STRIDE + 4]);
#pragma unroll
            for (int nf = 0; nf < 8; nf++) {
                const float* bp = Kb + (nf*8 + lr)*AK_STRIDE + kb*8 + lc;
                mma_tf32(sacc[nf][0], sacc[nf][1], sacc[nf][2], sacc[nf][3],
                         a0, a1, a2, a3,
                         __float_as_uint(bp[0]), __float_as_uint(bp[4]));
            }
        }

        // ---- causal mask (diag tile only) ----
        const int kvb = i*64;
        if (i == qb) {
#pragma unroll
            for (int nf = 0; nf < 8; nf++) {
                int col = kvb + nf*8 + 2*lc;
                if (col     > qrow0)     sacc[nf][0] = -1e30f;
                if (col + 1 > qrow0)     sacc[nf][1] = -1e30f;
                if (col     > qrow0 + 8) sacc[nf][2] = -1e30f;
                if (col + 1 > qrow0 + 8) sacc[nf][3] = -1e30f;
            }
        }

        // ---- online softmax ----
        float mx0 = -1e30f, mx1 = -1e30f;
#pragma unroll
        for (int nf = 0; nf < 8; nf++) {
            mx0 = fmaxf(mx0, fmaxf(sacc[nf][0], sacc[nf][1]));
            mx1 = fmaxf(mx1, fmaxf(sacc[nf][2], sacc[nf][3]));
        }
        mx0 = fmaxf(mx0, __shfl_xor_sync(0xffffffffu, mx0, 1));
        mx0 = fmaxf(mx0, __shfl_xor_sync(0xffffffffu, mx0, 2));
        mx1 = fmaxf(mx1, __shfl_xor_sync(0xffffffffu, mx1, 1));
        mx1 = fmaxf(mx1, __shfl_xor_sync(0xffffffffu, mx1, 2));
        float mn0 = fmaxf(m0, mx0), mn1 = fmaxf(m1, mx1);
        float al0 = __expf(m0 - mn0), al1 = __expf(m1 - mn1);
        m0 = mn0; m1 = mn1;

        float* Pw = sm + APS + (w*16)*AP_STRIDE;
        float rs0 = 0.f, rs1 = 0.f;
#pragma unroll
        for (int nf = 0; nf < 8; nf++) {
            float p0 = __expf(sacc[nf][0] - mn0);
            float p1 = __expf(sacc[nf][1] - mn0);
            float p2 = __expf(sacc[nf][2] - mn1);
            float p3 = __expf(sacc[nf][3] - mn1);
            rs0 += p0 + p1; rs1 += p2 + p3;
            *(float2*)&Pw[lr*AP_STRIDE + nf*8 + 2*lc]     = make_float2(tf32f(p0), tf32f(p1));
            *(float2*)&Pw[(lr+8)*AP_STRIDE + nf*8 + 2*lc] = make_float2(tf32f(p2), tf32f(p3));
        }
        rs0 += __shfl_xor_sync(0xffffffffu, rs0, 1);
        rs0 += __shfl_xor_sync(0xffffffffu, rs0, 2);
        rs1 += __shfl_xor_sync(0xffffffffu, rs1, 1);
        rs1 += __shfl_xor_sync(0xffffffffu, rs1, 2);
        l0 = l0*al0 + rs0; l1 = l1*al1 + rs1;
#pragma unroll
        for (int nf = 0; nf < 16; nf++) {
            oacc[nf][0] *= al0; oacc[nf][1] *= al0;
            oacc[nf][2] *= al1; oacc[nf][3] *= al1;
        }
        __syncwarp();

        // ---- O += P @ V ----
        const float* Vb = sm + AVS + (i & 1)*64*AV_STRIDE;
#pragma unroll
        for (int kb = 0; kb < 8; kb++) {
            const float* ap = Pw + lr*AP_STRIDE + kb*8 + lc;
            uint32_t a0 = __float_as_uint(ap[0]);
            uint32_t a1 = __float_as_uint(ap[8*AP_STRIDE]);
            uint32_t a2 = __float_as_uint(ap[4]);
            uint32_t a3 = __float_as_uint(ap[8*AP_STRIDE + 4]);
#pragma unroll
            for (int nf = 0; nf < 16; nf++) {
                const float* bp = Vb + (kb*8 + lc)*AV_STRIDE + nf*8 + lr;
                mma_tf32(oacc[nf][0], oacc[nf][1], oacc[nf][2], oacc[nf][3],
                         a0, a1, a2, a3,
                         __float_as_uint(bp[0]), __float_as_uint(bp[4*AV_STRIDE]));
            }
        }
        // no trailing barrier: next iter's leading barrier protects buffer reuse
    }

    float inv0 = 1.f / l0, inv1 = 1.f / l1;
    float* Ob = O + ((size_t)b*TQ + q0 + w*16)*DMODEL + h*HDIM;
#pragma unroll
    for (int nf = 0; nf < 16; nf++) {
        int col = nf*8 + 2*lc;
        *(float2*)(Ob + (size_t)lr*2048 + col) =
            make_float2(tf32f(oacc[nf][0]*inv0), tf32f(oacc[nf][1]*inv0));
        *(float2*)(Ob + (size_t)(lr+8)*2048 + col) =
            make_float2(tf32f(oacc[nf][2]*inv1), tf32f(oacc[nf][3]*inv1));
    }
}

// ---------------------------------------------------------------------------
// new_k / new_v permute (unchanged)
// ---------------------------------------------------------------------------
__global__ void permute_kv(const float* __restrict__ cache,
                           const float* __restrict__ proj,
                           float* __restrict__ out)
{
    int idx = blockIdx.x * blockDim.x + threadIdx.x;
    int j4  = idx & 511;
    int rem = idx >> 9;
    int i   = rem & 2047;
    int b   = rem >> 11;
    int j   = j4 << 2;
    int t   = (i & 127)*16 + (j >> 7);
    int c   = ((i >> 7) << 7) | (j & 127);
    const float* src = (t < CACHE)
        ? (cache + ((size_t)b*CACHE + t)*DMODEL + c)
        : (proj  + ((size_t)b*TQ + (t - CACHE))*DMODEL + c);
    ((float4*)out)[idx] = *(const float4*)src;
}

// ---------------------------------------------------------------------------
extern "C" void kernel_launch(void* const* d_in, const int* in_sizes, int n_in,
                              void* d_out, int out_size)
{
    const float* query  = (const float*)d_in[0];
    const float* key    = (const float*)d_in[1];
    const float* value  = (const float*)d_in[2];
    const float* cachek = (const float*)d_in[3];
    const float* cachev = (const float*)d_in[4];
    const float* Wq = (const float*)d_in[5];  const float* bq = (const float*)d_in[6];
    const float* Wk = (const float*)d_in[7];  const float* bk = (const float*)d_in[8];
    const float* Wv = (const float*)d_in[9];  const float* bv = (const float*)d_in[10];
    const float* Wo = (const float*)d_in[11]; const float* bo = (const float*)d_in[12];
    float* out = (float*)d_out;

    float *qp, *kp, *vp, *ap, *qr, *kr, *vr, *ckr, *cvr, *wqr, *wkr, *wvr, *wor;
    cudaGetSymbolAddress((void**)&qp,  g_qproj);
    cudaGetSymbolAddress((void**)&kp,  g_kproj);
    cudaGetSymbolAddress((void**)&vp,  g_vproj);
    cudaGetSymbolAddress((void**)&ap,  g_attn);
    cudaGetSymbolAddress((void**)&qr,  g_qr);
    cudaGetSymbolAddress((void**)&kr,  g_kr);
    cudaGetSymbolAddress((void**)&vr,  g_vr);
    cudaGetSymbolAddress((void**)&ckr, g_ckr);
    cudaGetSymbolAddress((void**)&cvr, g_cvr);
    cudaGetSymbolAddress((void**)&wqr, g_wqr);
    cudaGetSymbolAddress((void**)&wkr, g_wkr);
    cudaGetSymbolAddress((void**)&wvr, g_wvr);
    cudaGetSymbolAddress((void**)&wor, g_wor);

    // prep: tf32-round operands (2 launches)
    const int ACT4 = MROWS*DMODEL/4;        // 2097152
    const int W4   = DMODEL*DMODEL/4;       // 1048576
    round5_kernel<<<dim3(ACT4/256, 5), 256>>>(query, qr, key, kr, value, vr,
                                              cachek, ckr, cachev, cvr);
    round4_kernel<<<dim3(W4/256, 4), 256>>>(Wq, wqr, Wk, wkr, Wv, wvr, Wo, wor);

    cudaFuncSetAttribute(gemm_tf32, cudaFuncAttributeMaxDynamicSharedMemorySize, GEMM_SMEM);

    // merged QKV projections (grid.z = 3)
    GemmSet sq{qr, wqr, bq, qp, INV_SCALE, 1};
    GemmSet sk{kr, wkr, bk, kp, 1.f, 0};
    GemmSet sv{vr, wvr, bv, vp, 1.f, 0};
    gemm_tf32<<<dim3(16, 32, 3), 256, GEMM_SMEM>>>(sq, sk, sv);

    cudaFuncSetAttribute(attn_mma, cudaFuncAttributeMaxDynamicSharedMemorySize,
                         ATTN_FLOATS*4);
    attn_mma<<<dim3(TQ/64, BB*NHEADS), 128, ATTN_FLOATS*4>>>(qp, ckr, cvr, ap);

    // O projection
    GemmSet so{ap, wor, bo, out, 1.f, 0};
    gemm_tf32<<<dim3(16, 32, 1), 256, GEMM_SMEM>>>(so, so, so);

    permute_kv<<<4194304/256, 256>>>(cachek, kp, out + NEWK_OFF);
    permute_kv<<<4194304/256, 256>>>(cachev, vp, out + NEWV_OFF);
}

// round 8
// speedup vs baseline: 3.3211x; 1.0709x over previous
#include <cuda_runtime.h>
#include <cuda_bf16.h>
#include <math_constants.h>
#include <cstdint>

// Shapes
#define BB 4
#define TQ 1024
#define DMODEL 2048
#define NHEADS 16
#define HDIM 128
#define CACHE 1024
#define MROWS (BB*TQ)          // 4096
#define INV_SCALE 0.08838834764831843f  // 1/sqrt(128)

#define OUT_ELEMS   (BB*TQ*DMODEL)
#define NEWK_OFF    OUT_ELEMS
#define NEWV_OFF    (OUT_ELEMS + BB*2048*DMODEL)

// Scratch
__device__ float g_qproj[MROWS*DMODEL];
__device__ float g_kproj[MROWS*DMODEL];
__device__ float g_vproj[MROWS*DMODEL];
__device__ float g_attn [MROWS*DMODEL];
__device__ float g_qr   [MROWS*DMODEL];
__device__ float g_kr   [MROWS*DMODEL];
__device__ float g_vr   [MROWS*DMODEL];
__device__ float g_ckr  [BB*CACHE*DMODEL];
__device__ float g_cvr  [BB*CACHE*DMODEL];
__device__ float g_wqr  [DMODEL*DMODEL];
__device__ float g_wkr  [DMODEL*DMODEL];
__device__ float g_wvr  [DMODEL*DMODEL];
__device__ float g_wor  [DMODEL*DMODEL];

__device__ __forceinline__ uint32_t smem_u32(const void* p) {
    uint32_t a;
    asm("{ .reg .u64 t; cvta.to.shared.u64 t, %1; cvt.u32.u64 %0, t; }"
        : "=r"(a) : "l"(p));
    return a;
}
__device__ __forceinline__ void cp_async16(uint32_t dst, const void* src) {
    asm volatile("cp.async.cg.shared.global [%0], [%1], 16;" :: "r"(dst), "l"(src));
}
#define CP_COMMIT() asm volatile("cp.async.commit_group;" ::: "memory")
#define CP_WAIT2()  asm volatile("cp.async.wait_group 2;" ::: "memory")
#define CP_WAIT0()  asm volatile("cp.async.wait_group 0;" ::: "memory")

__device__ __forceinline__ uint32_t f2tf32(float f) {
    uint32_t r;
    asm("cvt.rna.tf32.f32 %0, %1;" : "=r"(r) : "f"(f));
    return r;
}
__device__ __forceinline__ float tf32f(float f) { return __uint_as_float(f2tf32(f)); }

__device__ __forceinline__ void mma_tf32(float& d0, float& d1, float& d2, float& d3,
                                         uint32_t a0, uint32_t a1, uint32_t a2, uint32_t a3,
                                         uint32_t b0, uint32_t b1)
{
    asm volatile(
        "mma.sync.aligned.m16n8k8.row.col.f32.tf32.tf32.f32 "
        "{%0,%1,%2,%3}, {%4,%5,%6,%7}, {%8,%9}, {%0,%1,%2,%3};"
        : "+f"(d0), "+f"(d1), "+f"(d2), "+f"(d3)
        : "r"(a0), "r"(a1), "r"(a2), "r"(a3), "r"(b0), "r"(b1));
}

// ===========================================================================
// prep: elementwise tf32 rounding (rna), float4 vectorized, multi-array
// ===========================================================================
__global__ void round5_kernel(const float* i0, float* o0, const float* i1, float* o1,
                              const float* i2, float* o2, const float* i3, float* o3,
                              const float* i4, float* o4)
{
    int idx = blockIdx.x * blockDim.x + threadIdx.x;
    const float* in; float* out;
    switch (blockIdx.y) {
        case 0: in = i0; out = o0; break;
        case 1: in = i1; out = o1; break;
        case 2: in = i2; out = o2; break;
        case 3: in = i3; out = o3; break;
        default: in = i4; out = o4; break;
    }
    float4 v = ((const float4*)in)[idx];
    v.x = tf32f(v.x); v.y = tf32f(v.y); v.z = tf32f(v.z); v.w = tf32f(v.w);
    ((float4*)out)[idx] = v;
}
__global__ void round4_kernel(const float* i0, float* o0, const float* i1, float* o1,
                              const float* i2, float* o2, const float* i3, float* o3)
{
    int idx = blockIdx.x * blockDim.x + threadIdx.x;
    const float* in; float* out;
    switch (blockIdx.y) {
        case 0: in = i0; out = o0; break;
        case 1: in = i1; out = o1; break;
        case 2: in = i2; out = o2; break;
        default: in = i3; out = o3; break;
    }
    float4 v = ((const float4*)in)[idx];
    v.x = tf32f(v.x); v.y = tf32f(v.y); v.z = tf32f(v.z); v.w = tf32f(v.w);
    ((float4*)out)[idx] = v;
}

// ===========================================================================
// mma.sync tf32 GEMM, CTA 128x256, warp tile 64x64 (2x4 warp grid), BK=32,
// 4-stage cp.async pipeline, single barrier per k-iter. grid.z selects
// operand set (merged QKV). Set with round_out applies scale + tf32 rounding.
// ===========================================================================
#define BK 32
#define STAGES 4
#define ROW_STRIDE 36
#define STAGE_ROWS 384                       // A 0..127, B 128..383
#define STAGE_FLOATS (STAGE_ROWS*ROW_STRIDE) // 13824
#define STAGE_BYTES  (STAGE_FLOATS*4)        // 55296
#define GEMM_SMEM    (STAGES*STAGE_BYTES)    // 221184

struct GemmSet { const float *A, *W, *bias; float *C; float scale; int round_out; };

__global__ __launch_bounds__(256, 1)
void gemm_tf32(GemmSet s0, GemmSet s1, GemmSet s2)
{
    const GemmSet& S = (blockIdx.z == 0) ? s0 : (blockIdx.z == 1) ? s1 : s2;
    const float* __restrict__ A = S.A;
    const float* __restrict__ W = S.W;
    const float* __restrict__ bias = S.bias;
    float* __restrict__ C = S.C;

    extern __shared__ __align__(128) float smem[];
    const uint32_t smem_addr = smem_u32(smem);
    const int tid  = threadIdx.x;
    const int wid  = tid >> 5;
    const int lane = tid & 31;
    const int bm = blockIdx.y * 128;
    const int bn = blockIdx.x * 256;
    const int wm = (wid & 1) * 64;       // warp M offset
    const int wn = (wid >> 1) * 64;      // warp N offset

    auto load_stage = [&](int it) {
        const int s  = it & (STAGES - 1);
        const int k0 = it * BK;
        const uint32_t sbase = smem_addr + s * STAGE_BYTES;
        const float* Ab = A + (size_t)bm * 2048 + k0;
        const float* Wb = W + (size_t)bn * 2048 + k0;
#pragma unroll
        for (int c = 0; c < 4; c++) {            // A: 1024 x 16B chunks
            int id = tid + c * 256;
            int row = id >> 3, seg = id & 7;
            cp_async16(sbase + row * (ROW_STRIDE*4) + seg * 16,
                       Ab + (size_t)row * 2048 + seg * 4);
        }
#pragma unroll
        for (int c = 0; c < 8; c++) {            // B: 2048 x 16B chunks
            int id = tid + c * 256;
            int row = id >> 3, seg = id & 7;
            cp_async16(sbase + (128 + row) * (ROW_STRIDE*4) + seg * 16,
                       Wb + (size_t)row * 2048 + seg * 4);
        }
    };

    float acc[4][8][4];
#pragma unroll
    for (int mf = 0; mf < 4; mf++)
#pragma unroll
        for (int nf = 0; nf < 8; nf++)
#pragma unroll
            for (int r = 0; r < 4; r++) acc[mf][nf][r] = 0.f;

    load_stage(0); CP_COMMIT();
    load_stage(1); CP_COMMIT();
    load_stage(2); CP_COMMIT();

    const int lr = lane >> 2;
    const int lc = lane & 3;

    for (int i = 0; i < 64; i++) {
        CP_WAIT2();               // stage i resident
        __syncthreads();          // everyone done reading buf (i-1)&3
        if (i + 3 < 64) load_stage(i + 3);
        CP_COMMIT();              // uniform group count (empty near tail)

        const float* As = smem + (size_t)(i & (STAGES-1)) * STAGE_FLOATS;
        const float* Bs = As + 128 * ROW_STRIDE;

#pragma unroll
        for (int ks = 0; ks < 4; ks++) {
            const int kb = ks * 8;
            uint32_t bfr[8][2];
#pragma unroll
            for (int nf = 0; nf < 8; nf++) {
                const float* bp = Bs + (wn + nf*8 + lr) * ROW_STRIDE + kb + lc;
                bfr[nf][0] = __float_as_uint(bp[0]);
                bfr[nf][1] = __float_as_uint(bp[4]);
            }
#pragma unroll
            for (int mf = 0; mf < 4; mf++) {
                const float* ap0 = As + (wm + mf*16 + lr) * ROW_STRIDE + kb + lc;
                const float* ap1 = ap0 + 8 * ROW_STRIDE;
                uint32_t a0 = __float_as_uint(ap0[0]);
                uint32_t a1 = __float_as_uint(ap1[0]);
                uint32_t a2 = __float_as_uint(ap0[4]);
                uint32_t a3 = __float_as_uint(ap1[4]);
#pragma unroll
                for (int nf = 0; nf < 8; nf++)
                    mma_tf32(acc[mf][nf][0], acc[mf][nf][1],
                             acc[mf][nf][2], acc[mf][nf][3],
                             a0, a1, a2, a3, bfr[nf][0], bfr[nf][1]);
            }
        }
        // no trailing barrier: next iter's leading barrier protects reuse
    }

    const float scale = S.scale;
    const int round_out = S.round_out;
#pragma unroll
    for (int nf = 0; nf < 8; nf++) {
        const int col = bn + wn + nf*8 + lc*2;
        const float b0 = bias[col], b1 = bias[col + 1];
#pragma unroll
        for (int mf = 0; mf < 4; mf++) {
            const int row0 = bm + wm + mf*16 + lr;
            float v0 = (acc[mf][nf][0] + b0) * scale;
            float v1 = (acc[mf][nf][1] + b1) * scale;
            float v2 = (acc[mf][nf][2] + b0) * scale;
            float v3 = (acc[mf][nf][3] + b1) * scale;
            if (round_out) { v0 = tf32f(v0); v1 = tf32f(v1); v2 = tf32f(v2); v3 = tf32f(v3); }
            *(float2*)(C + (size_t)row0 * 2048 + col)       = make_float2(v0, v1);
            *(float2*)(C + (size_t)(row0 + 8) * 2048 + col) = make_float2(v2, v3);
        }
    }
}

// ===========================================================================
// Tensor-core flash attention (tf32 mma), causal over cache only. (unchanged)
// ===========================================================================
#define AQ_STRIDE 132
#define AK_STRIDE 132
#define AV_STRIDE 136
#define AP_STRIDE 68
#define AQS 0
#define AKS (64*AQ_STRIDE)
#define AVS (AKS + 2*64*AK_STRIDE)
#define APS (AVS + 2*64*AV_STRIDE)
#define ATTN_FLOATS (APS + 64*AP_STRIDE)   // 47104 floats -> 188416 B

__global__ __launch_bounds__(128, 1)
void attn_mma(const float* __restrict__ Q,
              const float* __restrict__ K,
              const float* __restrict__ V,
              float* __restrict__ O)
{
    extern __shared__ __align__(128) float sm[];
    const uint32_t smaddr = smem_u32(sm);
    const int tid = threadIdx.x;
    const int w = tid >> 5, lane = tid & 31;
    const int lr = lane >> 2, lc = lane & 3;
    const int qb = gridDim.x - 1 - blockIdx.x;   // big tiles first
    const int bh = blockIdx.y;
    const int b = bh >> 4, h = bh & 15;
    const int q0 = qb * 64;
    const int nt = qb + 1;

    const float* Qg = Q + ((size_t)b*TQ + q0)*DMODEL + h*HDIM;
    const float* Kg = K + (size_t)b*CACHE*DMODEL + h*HDIM;
    const float* Vg = V + (size_t)b*CACHE*DMODEL + h*HDIM;

#pragma unroll
    for (int c = 0; c < 16; c++) {
        int id = tid + c*128;
        int row = id >> 5, c4 = (id & 31) << 2;
        float4 v = *(const float4*)(Qg + (size_t)row*2048 + c4);
        *(float4*)&sm[AQS + row*AQ_STRIDE + c4] = v;
    }

    auto load_kv = [&](int it) {
        const int s = it & 1;
        const int kv0 = it * 64;
        const uint32_t kd = smaddr + (AKS + s*64*AK_STRIDE)*4;
        const uint32_t vd = smaddr + (AVS + s*64*AV_STRIDE)*4;
        const float* Kt = Kg + (size_t)kv0*2048;
        const float* Vt = Vg + (size_t)kv0*2048;
#pragma unroll
        for (int c = 0; c < 16; c++) {
            int id = tid + c*128;
            int row = id >> 5, seg = id & 31;
            cp_async16(kd + row*(AK_STRIDE*4) + seg*16, Kt + (size_t)row*2048 + seg*4);
        }
#pragma unroll
        for (int c = 0; c < 16; c++) {
            int id = tid + c*128;
            int row = id >> 5, seg = id & 31;
            cp_async16(vd + row*(AV_STRIDE*4) + seg*16, Vt + (size_t)row*2048 + seg*4);
        }
    };

    load_kv(0); CP_COMMIT();

    float m0 = -1e30f, m1 = -1e30f, l0 = 0.f, l1 = 0.f;
    float oacc[16][4];
#pragma unroll
    for (int nf = 0; nf < 16; nf++)
#pragma unroll
        for (int r = 0; r < 4; r++) oacc[nf][r] = 0.f;

    const int qrow0 = q0 + w*16 + lr;

    for (int i = 0; i < nt; i++) {
        CP_WAIT0();
        __syncthreads();
        if (i + 1 < nt) { load_kv(i + 1); CP_COMMIT(); }

        // ---- S = Q K^T (pre-scaled) ----
        const float* Kb = sm + AKS + (i & 1)*64*AK_STRIDE;
        const float* Qw = sm + AQS + w*16*AQ_STRIDE;
        float sacc[8][4];
#pragma unroll
        for (int nf = 0; nf < 8; nf++)
#pragma unroll
            for (int r = 0; r < 4; r++) sacc[nf][r] = 0.f;

#pragma unroll
        for (int kb = 0; kb < 16; kb++) {
            const float* ap = Qw + lr*AQ_STRIDE + kb*8 + lc;
            uint32_t a0 = __float_as_uint(ap[0]);
            uint32_t a1 = __float_as_uint(ap[8*AQ_STRIDE]);
            uint32_t a2 = __float_as_uint(ap[4]);
            uint32_t a3 = __float_as_uint(ap[8*AQ_STRIDE + 4]);
#pragma unroll
            for (int nf = 0; nf < 8; nf++) {
                const float* bp = Kb + (nf*8 + lr)*AK_STRIDE + kb*8 + lc;
                mma_tf32(sacc[nf][0], sacc[nf][1], sacc[nf][2], sacc[nf][3],
                         a0, a1, a2, a3,
                         __float_as_uint(bp[0]), __float_as_uint(bp[4]));
            }
        }

        // ---- causal mask (diag tile only) ----
        const int kvb = i*64;
        if (i == qb) {
#pragma unroll
            for (int nf = 0; nf < 8; nf++) {
                int col = kvb + nf*8 + 2*lc;
                if (col     > qrow0)     sacc[nf][0] = -1e30f;
                if (col + 1 > qrow0)     sacc[nf][1] = -1e30f;
                if (col     > qrow0 + 8) sacc[nf][2] = -1e30f;
                if (col + 1 > qrow0 + 8) sacc[nf][3] = -1e30f;
            }
        }

        // ---- online softmax ----
        float mx0 = -1e30f, mx1 = -1e30f;
#pragma unroll
        for (int nf = 0; nf < 8; nf++) {
            mx0 = fmaxf(mx0, fmaxf(sacc[nf][0], sacc[nf][1]));
            mx1 = fmaxf(mx1, fmaxf(sacc[nf][2], sacc[nf][3]));
        }
        mx0 = fmaxf(mx0, __shfl_xor_sync(0xffffffffu, mx0, 1));
        mx0 = fmaxf(mx0, __shfl_xor_sync(0xffffffffu, mx0, 2));
        mx1 = fmaxf(mx1, __shfl_xor_sync(0xffffffffu, mx1, 1));
        mx1 = fmaxf(mx1, __shfl_xor_sync(0xffffffffu, mx1, 2));
        float mn0 = fmaxf(m0, mx0), mn1 = fmaxf(m1, mx1);
        float al0 = __expf(m0 - mn0), al1 = __expf(m1 - mn1);
        m0 = mn0; m1 = mn1;

        float* Pw = sm + APS + (w*16)*AP_STRIDE;
        float rs0 = 0.f, rs1 = 0.f;
#pragma unroll
        for (int nf = 0; nf < 8; nf++) {
            float p0 = __expf(sacc[nf][0] - mn0);
            float p1 = __expf(sacc[nf][1] - mn0);
            float p2 = __expf(sacc[nf][2] - mn1);
            float p3 = __expf(sacc[nf][3] - mn1);
            rs0 += p0 + p1; rs1 += p2 + p3;
            *(float2*)&Pw[lr*AP_STRIDE + nf*8 + 2*lc]     = make_float2(tf32f(p0), tf32f(p1));
            *(float2*)&Pw[(lr+8)*AP_STRIDE + nf*8 + 2*lc] = make_float2(tf32f(p2), tf32f(p3));
        }
        rs0 += __shfl_xor_sync(0xffffffffu, rs0, 1);
        rs0 += __shfl_xor_sync(0xffffffffu, rs0, 2);
        rs1 += __shfl_xor_sync(0xffffffffu, rs1, 1);
        rs1 += __shfl_xor_sync(0xffffffffu, rs1, 2);
        l0 = l0*al0 + rs0; l1 = l1*al1 + rs1;
#pragma unroll
        for (int nf = 0; nf < 16; nf++) {
            oacc[nf][0] *= al0; oacc[nf][1] *= al0;
            oacc[nf][2] *= al1; oacc[nf][3] *= al1;
        }
        __syncwarp();

        // ---- O += P @ V ----
        const float* Vb = sm + AVS + (i & 1)*64*AV_STRIDE;
#pragma unroll
        for (int kb = 0; kb < 8; kb++) {
            const float* ap = Pw + lr*AP_STRIDE + kb*8 + lc;
            uint32_t a0 = __float_as_uint(ap[0]);
            uint32_t a1 = __float_as_uint(ap[8*AP_STRIDE]);
            uint32_t a2 = __float_as_uint(ap[4]);
            uint32_t a3 = __float_as_uint(ap[8*AP_STRIDE + 4]);
#pragma unroll
            for (int nf = 0; nf < 16; nf++) {
                const float* bp = Vb + (kb*8 + lc)*AV_STRIDE + nf*8 + lr;
                mma_tf32(oacc[nf][0], oacc[nf][1], oacc[nf][2], oacc[nf][3],
                         a0, a1, a2, a3,
                         __float_as_uint(bp[0]), __float_as_uint(bp[4*AV_STRIDE]));
            }
        }
    }

    float inv0 = 1.f / l0, inv1 = 1.f / l1;
    float* Ob = O + ((size_t)b*TQ + q0 + w*16)*DMODEL + h*HDIM;
#pragma unroll
    for (int nf = 0; nf < 16; nf++) {
        int col = nf*8 + 2*lc;
        *(float2*)(Ob + (size_t)lr*2048 + col) =
            make_float2(tf32f(oacc[nf][0]*inv0), tf32f(oacc[nf][1]*inv0));
        *(float2*)(Ob + (size_t)(lr+8)*2048 + col) =
            make_float2(tf32f(oacc[nf][2]*inv1), tf32f(oacc[nf][3]*inv1));
    }
}

// ---------------------------------------------------------------------------
// new_k / new_v permute (unchanged)
// ---------------------------------------------------------------------------
__global__ void permute_kv(const float* __restrict__ cache,
                           const float* __restrict__ proj,
                           float* __restrict__ out)
{
    int idx = blockIdx.x * blockDim.x + threadIdx.x;
    int j4  = idx & 511;
    int rem = idx >> 9;
    int i   = rem & 2047;
    int b   = rem >> 11;
    int j   = j4 << 2;
    int t   = (i & 127)*16 + (j >> 7);
    int c   = ((i >> 7) << 7) | (j & 127);
    const float* src = (t < CACHE)
        ? (cache + ((size_t)b*CACHE + t)*DMODEL + c)
        : (proj  + ((size_t)b*TQ + (t - CACHE))*DMODEL + c);
    ((float4*)out)[idx] = *(const float4*)src;
}

// ---------------------------------------------------------------------------
extern "C" void kernel_launch(void* const* d_in, const int* in_sizes, int n_in,
                              void* d_out, int out_size)
{
    const float* query  = (const float*)d_in[0];
    const float* key    = (const float*)d_in[1];
    const float* value  = (const float*)d_in[2];
    const float* cachek = (const float*)d_in[3];
    const float* cachev = (const float*)d_in[4];
    const float* Wq = (const float*)d_in[5];  const float* bq = (const float*)d_in[6];
    const float* Wk = (const float*)d_in[7];  const float* bk = (const float*)d_in[8];
    const float* Wv = (const float*)d_in[9];  const float* bv = (const float*)d_in[10];
    const float* Wo = (const float*)d_in[11]; const float* bo = (const float*)d_in[12];
    float* out = (float*)d_out;

    float *qp, *kp, *vp, *ap, *qr, *kr, *vr, *ckr, *cvr, *wqr, *wkr, *wvr, *wor;
    cudaGetSymbolAddress((void**)&qp,  g_qproj);
    cudaGetSymbolAddress((void**)&kp,  g_kproj);
    cudaGetSymbolAddress((void**)&vp,  g_vproj);
    cudaGetSymbolAddress((void**)&ap,  g_attn);
    cudaGetSymbolAddress((void**)&qr,  g_qr);
    cudaGetSymbolAddress((void**)&kr,  g_kr);
    cudaGetSymbolAddress((void**)&vr,  g_vr);
    cudaGetSymbolAddress((void**)&ckr, g_ckr);
    cudaGetSymbolAddress((void**)&cvr, g_cvr);
    cudaGetSymbolAddress((void**)&wqr, g_wqr);
    cudaGetSymbolAddress((void**)&wkr, g_wkr);
    cudaGetSymbolAddress((void**)&wvr, g_wvr);
    cudaGetSymbolAddress((void**)&wor, g_wor);

    // prep: tf32-round operands (2 launches)
    const int ACT4 = MROWS*DMODEL/4;        // 2097152
    const int W4   = DMODEL*DMODEL/4;       // 1048576
    round5_kernel<<<dim3(ACT4/256, 5), 256>>>(query, qr, key, kr, value, vr,
                                              cachek, ckr, cachev, cvr);
    round4_kernel<<<dim3(W4/256, 4), 256>>>(Wq, wqr, Wk, wkr, Wv, wvr, Wo, wor);

    cudaFuncSetAttribute(gemm_tf32, cudaFuncAttributeMaxDynamicSharedMemorySize, GEMM_SMEM);

    // merged QKV projections (grid.z = 3), CTA tile 128x256
    GemmSet sq{qr, wqr, bq, qp, INV_SCALE, 1};
    GemmSet sk{kr, wkr, bk, kp, 1.f, 0};
    GemmSet sv{vr, wvr, bv, vp, 1.f, 0};
    gemm_tf32<<<dim3(8, 32, 3), 256, GEMM_SMEM>>>(sq, sk, sv);

    cudaFuncSetAttribute(attn_mma, cudaFuncAttributeMaxDynamicSharedMemorySize,
                         ATTN_FLOATS*4);
    attn_mma<<<dim3(TQ/64, BB*NHEADS), 128, ATTN_FLOATS*4>>>(qp, ckr, cvr, ap);

    // O projection
    GemmSet so{ap, wor, bo, out, 1.f, 0};
    gemm_tf32<<<dim3(8, 32, 1), 256, GEMM_SMEM>>>(so, so, so);

    permute_kv<<<4194304/256, 256>>>(cachek, kp, out + NEWK_OFF);
    permute_kv<<<4194304/256, 256>>>(cachev, vp, out + NEWV_OFF);
}

// round 9
// speedup vs baseline: 3.3872x; 1.0199x over previous
#include <cuda_runtime.h>
#include <cuda_bf16.h>
#include <math_constants.h>
#include <cstdint>

// Shapes
#define BB 4
#define TQ 1024
#define DMODEL 2048
#define NHEADS 16
#define HDIM 128
#define CACHE 1024
#define MROWS (BB*TQ)          // 4096
#define INV_SCALE 0.08838834764831843f  // 1/sqrt(128)

#define OUT_ELEMS   (BB*TQ*DMODEL)
#define NEWK_OFF    OUT_ELEMS
#define NEWV_OFF    (OUT_ELEMS + BB*2048*DMODEL)

// Scratch
__device__ float g_qproj[MROWS*DMODEL];
__device__ float g_attn [MROWS*DMODEL];
__device__ float g_qr   [MROWS*DMODEL];
__device__ float g_kr   [MROWS*DMODEL];
__device__ float g_vr   [MROWS*DMODEL];
__device__ float g_ckr  [BB*CACHE*DMODEL];
__device__ float g_cvr  [BB*CACHE*DMODEL];
__device__ float g_wqr  [DMODEL*DMODEL];
__device__ float g_wkr  [DMODEL*DMODEL];
__device__ float g_wvr  [DMODEL*DMODEL];
__device__ float g_wor  [DMODEL*DMODEL];

__device__ __forceinline__ uint32_t smem_u32(const void* p) {
    uint32_t a;
    asm("{ .reg .u64 t; cvta.to.shared.u64 t, %1; cvt.u32.u64 %0, t; }"
        : "=r"(a) : "l"(p));
    return a;
}
__device__ __forceinline__ void cp_async16(uint32_t dst, const void* src) {
    asm volatile("cp.async.cg.shared.global [%0], [%1], 16;" :: "r"(dst), "l"(src));
}
#define CP_COMMIT() asm volatile("cp.async.commit_group;" ::: "memory")
#define CP_WAIT2()  asm volatile("cp.async.wait_group 2;" ::: "memory")
#define CP_WAIT0()  asm volatile("cp.async.wait_group 0;" ::: "memory")

__device__ __forceinline__ uint32_t f2tf32(float f) {
    uint32_t r;
    asm("cvt.rna.tf32.f32 %0, %1;" : "=r"(r) : "f"(f));
    return r;
}
__device__ __forceinline__ float tf32f(float f) { return __uint_as_float(f2tf32(f)); }

__device__ __forceinline__ void mma_tf32(float& d0, float& d1, float& d2, float& d3,
                                         uint32_t a0, uint32_t a1, uint32_t a2, uint32_t a3,
                                         uint32_t b0, uint32_t b1)
{
    asm volatile(
        "mma.sync.aligned.m16n8k8.row.col.f32.tf32.tf32.f32 "
        "{%0,%1,%2,%3}, {%4,%5,%6,%7}, {%8,%9}, {%0,%1,%2,%3};"
        : "+f"(d0), "+f"(d1), "+f"(d2), "+f"(d3)
        : "r"(a0), "r"(a1), "r"(a2), "r"(a3), "r"(b0), "r"(b1));
}

// ===========================================================================
// prep: elementwise tf32 rounding (rna), float4 vectorized, multi-array
// ===========================================================================
__global__ void round5_kernel(const float* i0, float* o0, const float* i1, float* o1,
                              const float* i2, float* o2, const float* i3, float* o3,
                              const float* i4, float* o4)
{
    int idx = blockIdx.x * blockDim.x + threadIdx.x;
    const float* in; float* out;
    switch (blockIdx.y) {
        case 0: in = i0; out = o0; break;
        case 1: in = i1; out = o1; break;
        case 2: in = i2; out = o2; break;
        case 3: in = i3; out = o3; break;
        default: in = i4; out = o4; break;
    }
    float4 v = ((const float4*)in)[idx];
    v.x = tf32f(v.x); v.y = tf32f(v.y); v.z = tf32f(v.z); v.w = tf32f(v.w);
    ((float4*)out)[idx] = v;
}
__global__ void round4_kernel(const float* i0, float* o0, const float* i1, float* o1,
                              const float* i2, float* o2, const float* i3, float* o3)
{
    int idx = blockIdx.x * blockDim.x + threadIdx.x;
    const float* in; float* out;
    switch (blockIdx.y) {
        case 0: in = i0; out = o0; break;
        case 1: in = i1; out = o1; break;
        case 2: in = i2; out = o2; break;
        default: in = i3; out = o3; break;
    }
    float4 v = ((const float4*)in)[idx];
    v.x = tf32f(v.x); v.y = tf32f(v.y); v.z = tf32f(v.z); v.w = tf32f(v.w);
    ((float4*)out)[idx] = v;
}

// ===========================================================================
// mma.sync tf32 GEMM, CTA 128x256, warp tile 64x64, BK=32, 4-stage cp.async,
// single barrier per k-iter, register double-buffered fragments.
// Epilogue modes: normal (scale + optional tf32 round) or permuted scatter
// (K/V projections write directly into new_k/new_v layout).
// ===========================================================================
#define BK 32
#define STAGES 4
#define ROW_STRIDE 36
#define STAGE_ROWS 384
#define STAGE_FLOATS (STAGE_ROWS*ROW_STRIDE) // 13824
#define STAGE_BYTES  (STAGE_FLOATS*4)        // 55296
#define GEMM_SMEM    (STAGES*STAGE_BYTES)    // 221184

struct GemmSet { const float *A, *W, *bias; float *C; float scale; int round_out; int permute_out; };

__global__ __launch_bounds__(256, 1)
void gemm_tf32(GemmSet s0, GemmSet s1, GemmSet s2)
{
    const GemmSet& S = (blockIdx.z == 0) ? s0 : (blockIdx.z == 1) ? s1 : s2;
    const float* __restrict__ A = S.A;
    const float* __restrict__ W = S.W;
    const float* __restrict__ bias = S.bias;
    float* __restrict__ C = S.C;

    extern __shared__ __align__(128) float smem[];
    const uint32_t smem_addr = smem_u32(smem);
    const int tid  = threadIdx.x;
    const int wid  = tid >> 5;
    const int lane = tid & 31;
    const int bm = blockIdx.y * 128;
    const int bn = blockIdx.x * 256;
    const int wm = (wid & 1) * 64;
    const int wn = (wid >> 1) * 64;

    auto load_stage = [&](int it) {
        const int s  = it & (STAGES - 1);
        const int k0 = it * BK;
        const uint32_t sbase = smem_addr + s * STAGE_BYTES;
        const float* Ab = A + (size_t)bm * 2048 + k0;
        const float* Wb = W + (size_t)bn * 2048 + k0;
#pragma unroll
        for (int c = 0; c < 4; c++) {
            int id = tid + c * 256;
            int row = id >> 3, seg = id & 7;
            cp_async16(sbase + row * (ROW_STRIDE*4) + seg * 16,
                       Ab + (size_t)row * 2048 + seg * 4);
        }
#pragma unroll
        for (int c = 0; c < 8; c++) {
            int id = tid + c * 256;
            int row = id >> 3, seg = id & 7;
            cp_async16(sbase + (128 + row) * (ROW_STRIDE*4) + seg * 16,
                       Wb + (size_t)row * 2048 + seg * 4);
        }
    };

    float acc[4][8][4];
#pragma unroll
    for (int mf = 0; mf < 4; mf++)
#pragma unroll
        for (int nf = 0; nf < 8; nf++)
#pragma unroll
            for (int r = 0; r < 4; r++) acc[mf][nf][r] = 0.f;

    load_stage(0); CP_COMMIT();
    load_stage(1); CP_COMMIT();
    load_stage(2); CP_COMMIT();

    const int lr = lane >> 2;
    const int lc = lane & 3;

    uint32_t afr[2][4][4], bfr[2][8][2];

    auto load_frags = [&](const float* As, const float* Bs, int ks,
                          uint32_t (&af)[4][4], uint32_t (&bf)[8][2]) {
        const int kb = ks * 8;
#pragma unroll
        for (int nf = 0; nf < 8; nf++) {
            const float* bp = Bs + (wn + nf*8 + lr) * ROW_STRIDE + kb + lc;
            bf[nf][0] = __float_as_uint(bp[0]);
            bf[nf][1] = __float_as_uint(bp[4]);
        }
#pragma unroll
        for (int mf = 0; mf < 4; mf++) {
            const float* ap = As + (wm + mf*16 + lr) * ROW_STRIDE + kb + lc;
            af[mf][0] = __float_as_uint(ap[0]);
            af[mf][1] = __float_as_uint(ap[8*ROW_STRIDE]);
            af[mf][2] = __float_as_uint(ap[4]);
            af[mf][3] = __float_as_uint(ap[8*ROW_STRIDE + 4]);
        }
    };

    for (int i = 0; i < 64; i++) {
        CP_WAIT2();               // stage i resident
        __syncthreads();          // everyone done reading buf (i-1)&3
        if (i + 3 < 64) load_stage(i + 3);
        CP_COMMIT();              // uniform group count

        const float* As = smem + (size_t)(i & (STAGES-1)) * STAGE_FLOATS;
        const float* Bs = As + 128 * ROW_STRIDE;

        load_frags(As, Bs, 0, afr[0], bfr[0]);
#pragma unroll
        for (int ks = 0; ks < 4; ks++) {
            const int cur = ks & 1;
            if (ks < 3) load_frags(As, Bs, ks + 1, afr[cur^1], bfr[cur^1]);
#pragma unroll
            for (int mf = 0; mf < 4; mf++)
#pragma unroll
                for (int nf = 0; nf < 8; nf++)
                    mma_tf32(acc[mf][nf][0], acc[mf][nf][1],
                             acc[mf][nf][2], acc[mf][nf][3],
                             afr[cur][mf][0], afr[cur][mf][1],
                             afr[cur][mf][2], afr[cur][mf][3],
                             bfr[cur][nf][0], bfr[cur][nf][1]);
        }
        // no trailing barrier: next iter's leading barrier protects reuse
    }

    if (S.permute_out) {
        // scatter-store into new_k/new_v layout:
        // row = b*1024 + tq, col = c  ->  i = (c>>7)<<7 | 64 | (tq>>4),
        //                                 j = (tq&15)<<7 | (c&127)
#pragma unroll
        for (int nf = 0; nf < 8; nf++) {
            const int col = bn + wn + nf*8 + lc*2;
            const float b0 = bias[col], b1 = bias[col + 1];
            const int ch = (col >> 7) << 7;
            const int cl = col & 127;
#pragma unroll
            for (int mf = 0; mf < 4; mf++) {
                const int row0 = bm + wm + mf*16 + lr;
#pragma unroll
                for (int rr = 0; rr < 2; rr++) {
                    const int row = row0 + rr*8;
                    const int bb = row >> 10, tq = row & 1023;
                    const int ii = ch | 64 | (tq >> 4);
                    const int jj = ((tq & 15) << 7) | cl;
                    float v0 = acc[mf][nf][rr*2+0] + b0;
                    float v1 = acc[mf][nf][rr*2+1] + b1;
                    *(float2*)(C + (((size_t)((bb << 11) | ii)) << 11) + jj) =
                        make_float2(v0, v1);
                }
            }
        }
    } else {
        const float scale = S.scale;
        const int round_out = S.round_out;
#pragma unroll
        for (int nf = 0; nf < 8; nf++) {
            const int col = bn + wn + nf*8 + lc*2;
            const float b0 = bias[col], b1 = bias[col + 1];
#pragma unroll
            for (int mf = 0; mf < 4; mf++) {
                const int row0 = bm + wm + mf*16 + lr;
                float v0 = (acc[mf][nf][0] + b0) * scale;
                float v1 = (acc[mf][nf][1] + b1) * scale;
                float v2 = (acc[mf][nf][2] + b0) * scale;
                float v3 = (acc[mf][nf][3] + b1) * scale;
                if (round_out) { v0 = tf32f(v0); v1 = tf32f(v1); v2 = tf32f(v2); v3 = tf32f(v3); }
                *(float2*)(C + (size_t)row0 * 2048 + col)       = make_float2(v0, v1);
                *(float2*)(C + (size_t)(row0 + 8) * 2048 + col) = make_float2(v2, v3);
            }
        }
    }
}

// ===========================================================================
// Tensor-core flash attention (tf32 mma), causal over cache only. (unchanged)
// ===========================================================================
#define AQ_STRIDE 132
#define AK_STRIDE 132
#define AV_STRIDE 136
#define AP_STRIDE 68
#define AQS 0
#define AKS (64*AQ_STRIDE)
#define AVS (AKS + 2*64*AK_STRIDE)
#define APS (AVS + 2*64*AV_STRIDE)
#define ATTN_FLOATS (APS + 64*AP_STRIDE)   // 47104 floats -> 188416 B

__global__ __launch_bounds__(128, 1)
void attn_mma(const float* __restrict__ Q,
              const float* __restrict__ K,
              const float* __restrict__ V,
              float* __restrict__ O)
{
    extern __shared__ __align__(128) float sm[];
    const uint32_t smaddr = smem_u32(sm);
    const int tid = threadIdx.x;
    const int w = tid >> 5, lane = tid & 31;
    const int lr = lane >> 2, lc = lane & 3;
    const int qb = gridDim.x - 1 - blockIdx.x;   // big tiles first
    const int bh = blockIdx.y;
    const int b = bh >> 4, h = bh & 15;
    const int q0 = qb * 64;
    const int nt = qb + 1;

    const float* Qg = Q + ((size_t)b*TQ + q0)*DMODEL + h*HDIM;
    const float* Kg = K + (size_t)b*CACHE*DMODEL + h*HDIM;
    const float* Vg = V + (size_t)b*CACHE*DMODEL + h*HDIM;

#pragma unroll
    for (int c = 0; c < 16; c++) {
        int id = tid + c*128;
        int row = id >> 5, c4 = (id & 31) << 2;
        float4 v = *(const float4*)(Qg + (size_t)row*2048 + c4);
        *(float4*)&sm[AQS + row*AQ_STRIDE + c4] = v;
    }

    auto load_kv = [&](int it) {
        const int s = it & 1;
        const int kv0 = it * 64;
        const uint32_t kd = smaddr + (AKS + s*64*AK_STRIDE)*4;
        const uint32_t vd = smaddr + (AVS + s*64*AV_STRIDE)*4;
        const float* Kt = Kg + (size_t)kv0*2048;
        const float* Vt = Vg + (size_t)kv0*2048;
#pragma unroll
        for (int c = 0; c < 16; c++) {
            int id = tid + c*128;
            int row = id >> 5, seg = id & 31;
            cp_async16(kd + row*(AK_STRIDE*4) + seg*16, Kt + (size_t)row*2048 + seg*4);
        }
#pragma unroll
        for (int c = 0; c < 16; c++) {
            int id = tid + c*128;
            int row = id >> 5, seg = id & 31;
            cp_async16(vd + row*(AV_STRIDE*4) + seg*16, Vt + (size_t)row*2048 + seg*4);
        }
    };

    load_kv(0); CP_COMMIT();

    float m0 = -1e30f, m1 = -1e30f, l0 = 0.f, l1 = 0.f;
    float oacc[16][4];
#pragma unroll
    for (int nf = 0; nf < 16; nf++)
#pragma unroll
        for (int r = 0; r < 4; r++) oacc[nf][r] = 0.f;

    const int qrow0 = q0 + w*16 + lr;

    for (int i = 0; i < nt; i++) {
        CP_WAIT0();
        __syncthreads();
        if (i + 1 < nt) { load_kv(i + 1); CP_COMMIT(); }

        // ---- S = Q K^T (pre-scaled) ----
        const float* Kb = sm + AKS + (i & 1)*64*AK_STRIDE;
        const float* Qw = sm + AQS + w*16*AQ_STRIDE;
        float sacc[8][4];
#pragma unroll
        for (int nf = 0; nf < 8; nf++)
#pragma unroll
            for (int r = 0; r < 4; r++) sacc[nf][r] = 0.f;

#pragma unroll
        for (int kb = 0; kb < 16; kb++) {
            const float* ap = Qw + lr*AQ_STRIDE + kb*8 + lc;
            uint32_t a0 = __float_as_uint(ap[0]);
            uint32_t a1 = __float_as_uint(ap[8*AQ_STRIDE]);
            uint32_t a2 = __float_as_uint(ap[4]);
            uint32_t a3 = __float_as_uint(ap[8*AQ_STRIDE + 4]);
#pragma unroll
            for (int nf = 0; nf < 8; nf++) {
                const float* bp = Kb + (nf*8 + lr)*AK_STRIDE + kb*8 + lc;
                mma_tf32(sacc[nf][0], sacc[nf][1], sacc[nf][2], sacc[nf][3],
                         a0, a1, a2, a3,
                         __float_as_uint(bp[0]), __float_as_uint(bp[4]));
            }
        }

        // ---- causal mask (diag tile only) ----
        const int kvb = i*64;
        if (i == qb) {
#pragma unroll
            for (int nf = 0; nf < 8; nf++) {
                int col = kvb + nf*8 + 2*lc;
                if (col     > qrow0)     sacc[nf][0] = -1e30f;
                if (col + 1 > qrow0)     sacc[nf][1] = -1e30f;
                if (col     > qrow0 + 8) sacc[nf][2] = -1e30f;
                if (col + 1 > qrow0 + 8) sacc[nf][3] = -1e30f;
            }
        }

        // ---- online softmax ----
        float mx0 = -1e30f, mx1 = -1e30f;
#pragma unroll
        for (int nf = 0; nf < 8; nf++) {
            mx0 = fmaxf(mx0, fmaxf(sacc[nf][0], sacc[nf][1]));
            mx1 = fmaxf(mx1, fmaxf(sacc[nf][2], sacc[nf][3]));
        }
        mx0 = fmaxf(mx0, __shfl_xor_sync(0xffffffffu, mx0, 1));
        mx0 = fmaxf(mx0, __shfl_xor_sync(0xffffffffu, mx0, 2));
        mx1 = fmaxf(mx1, __shfl_xor_sync(0xffffffffu, mx1, 1));
        mx1 = fmaxf(mx1, __shfl_xor_sync(0xffffffffu, mx1, 2));
        float mn0 = fmaxf(m0, mx0), mn1 = fmaxf(m1, mx1);
        float al0 = __expf(m0 - mn0), al1 = __expf(m1 - mn1);
        m0 = mn0; m1 = mn1;

        float* Pw = sm + APS + (w*16)*AP_STRIDE;
        float rs0 = 0.f, rs1 = 0.f;
#pragma unroll
        for (int nf = 0; nf < 8; nf++) {
            float p0 = __expf(sacc[nf][0] - mn0);
            float p1 = __expf(sacc[nf][1] - mn0);
            float p2 = __expf(sacc[nf][2] - mn1);
            float p3 = __expf(sacc[nf][3] - mn1);
            rs0 += p0 + p1; rs1 += p2 + p3;
            *(float2*)&Pw[lr*AP_STRIDE + nf*8 + 2*lc]     = make_float2(tf32f(p0), tf32f(p1));
            *(float2*)&Pw[(lr+8)*AP_STRIDE + nf*8 + 2*lc] = make_float2(tf32f(p2), tf32f(p3));
        }
        rs0 += __shfl_xor_sync(0xffffffffu, rs0, 1);
        rs0 += __shfl_xor_sync(0xffffffffu, rs0, 2);
        rs1 += __shfl_xor_sync(0xffffffffu, rs1, 1);
        rs1 += __shfl_xor_sync(0xffffffffu, rs1, 2);
        l0 = l0*al0 + rs0; l1 = l1*al1 + rs1;
#pragma unroll
        for (int nf = 0; nf < 16; nf++) {
            oacc[nf][0] *= al0; oacc[nf][1] *= al0;
            oacc[nf][2] *= al1; oacc[nf][3] *= al1;
        }
        __syncwarp();

        // ---- O += P @ V ----
        const float* Vb = sm + AVS + (i & 1)*64*AV_STRIDE;
#pragma unroll
        for (int kb = 0; kb < 8; kb++) {
            const float* ap = Pw + lr*AP_STRIDE + kb*8 + lc;
            uint32_t a0 = __float_as_uint(ap[0]);
            uint32_t a1 = __float_as_uint(ap[8*AP_STRIDE]);
            uint32_t a2 = __float_as_uint(ap[4]);
            uint32_t a3 = __float_as_uint(ap[8*AP_STRIDE + 4]);
#pragma unroll
            for (int nf = 0; nf < 16; nf++) {
                const float* bp = Vb + (kb*8 + lc)*AV_STRIDE + nf*8 + lr;
                mma_tf32(oacc[nf][0], oacc[nf][1], oacc[nf][2], oacc[nf][3],
                         a0, a1, a2, a3,
                         __float_as_uint(bp[0]), __float_as_uint(bp[4*AV_STRIDE]));
            }
        }
    }

    float inv0 = 1.f / l0, inv1 = 1.f / l1;
    float* Ob = O + ((size_t)b*TQ + q0 + w*16)*DMODEL + h*HDIM;
#pragma unroll
    for (int nf = 0; nf < 16; nf++) {
        int col = nf*8 + 2*lc;
        *(float2*)(Ob + (size_t)lr*2048 + col) =
            make_float2(tf32f(oacc[nf][0]*inv0), tf32f(oacc[nf][1]*inv0));
        *(float2*)(Ob + (size_t)(lr+8)*2048 + col) =
            make_float2(tf32f(oacc[nf][2]*inv1), tf32f(oacc[nf][3]*inv1));
    }
}

// ---------------------------------------------------------------------------
// new_k / new_v permute, cache half only (t < 1024  <=>  (i&127) < 64).
// Proj half is written directly by the K/V GEMM epilogues.
// ---------------------------------------------------------------------------
__global__ void permute_cache(const float* __restrict__ cache,
                              float* __restrict__ out)
{
    int idx = blockIdx.x * blockDim.x + threadIdx.x;   // float4 chunks: 4*1024*512
    int j4  = idx & 511;
    int rem = idx >> 9;
    int ip  = rem & 1023;          // ih(4b)|il(6b)
    int b   = rem >> 10;
    int il  = ip & 63, ih = ip >> 6;
    int i   = (ih << 7) | il;
    int j   = j4 << 2;
    int t   = il*16 + (j >> 7);                 // < 1024
    int c   = (ih << 7) | (j & 127);
    float4 v = *(const float4*)(cache + ((size_t)b*CACHE + t)*DMODEL + c);
    *(float4*)(out + (((size_t)((b << 11) | i)) << 11) + j) = v;
}

// ---------------------------------------------------------------------------
extern "C" void kernel_launch(void* const* d_in, const int* in_sizes, int n_in,
                              void* d_out, int out_size)
{
    const float* query  = (const float*)d_in[0];
    const float* key    = (const float*)d_in[1];
    const float* value  = (const float*)d_in[2];
    const float* cachek = (const float*)d_in[3];
    const float* cachev = (const float*)d_in[4];
    const float* Wq = (const float*)d_in[5];  const float* bq = (const float*)d_in[6];
    const float* Wk = (const float*)d_in[7];  const float* bk = (const float*)d_in[8];
    const float* Wv = (const float*)d_in[9];  const float* bv = (const float*)d_in[10];
    const float* Wo = (const float*)d_in[11]; const float* bo = (const float*)d_in[12];
    float* out = (float*)d_out;

    float *qp, *ap, *qr, *kr, *vr, *ckr, *cvr, *wqr, *wkr, *wvr, *wor;
    cudaGetSymbolAddress((void**)&qp,  g_qproj);
    cudaGetSymbolAddress((void**)&ap,  g_attn);
    cudaGetSymbolAddress((void**)&qr,  g_qr);
    cudaGetSymbolAddress((void**)&kr,  g_kr);
    cudaGetSymbolAddress((void**)&vr,  g_vr);
    cudaGetSymbolAddress((void**)&ckr, g_ckr);
    cudaGetSymbolAddress((void**)&cvr, g_cvr);
    cudaGetSymbolAddress((void**)&wqr, g_wqr);
    cudaGetSymbolAddress((void**)&wkr, g_wkr);
    cudaGetSymbolAddress((void**)&wvr, g_wvr);
    cudaGetSymbolAddress((void**)&wor, g_wor);

    // prep: tf32-round operands (2 launches)
    const int ACT4 = MROWS*DMODEL/4;        // 2097152
    const int W4   = DMODEL*DMODEL/4;       // 1048576
    round5_kernel<<<dim3(ACT4/256, 5), 256>>>(query, qr, key, kr, value, vr,
                                              cachek, ckr, cachev, cvr);
    round4_kernel<<<dim3(W4/256, 4), 256>>>(Wq, wqr, Wk, wkr, Wv, wvr, Wo, wor);

    cudaFuncSetAttribute(gemm_tf32, cudaFuncAttributeMaxDynamicSharedMemorySize, GEMM_SMEM);

    // merged QKV projections (grid.z = 3); K/V scatter straight into new_k/new_v
    GemmSet sq{qr, wqr, bq, qp,              INV_SCALE, 1, 0};
    GemmSet sk{kr, wkr, bk, out + NEWK_OFF,  1.f,       0, 1};
    GemmSet sv{vr, wvr, bv, out + NEWV_OFF,  1.f,       0, 1};
    gemm_tf32<<<dim3(8, 32, 3), 256, GEMM_SMEM>>>(sq, sk, sv);

    cudaFuncSetAttribute(attn_mma, cudaFuncAttributeMaxDynamicSharedMemorySize,
                         ATTN_FLOATS*4);
    attn_mma<<<dim3(TQ/64, BB*NHEADS), 128, ATTN_FLOATS*4>>>(qp, ckr, cvr, ap);

    // O projection
    GemmSet so{ap, wor, bo, out, 1.f, 0, 0};
    gemm_tf32<<<dim3(8, 32, 1), 256, GEMM_SMEM>>>(so, so, so);

    // cache halves of new_k / new_v
    permute_cache<<<2097152/256, 256>>>(cachek, out + NEWK_OFF);
    permute_cache<<<2097152/256, 256>>>(cachev, out + NEWV_OFF);
}

// round 10
// speedup vs baseline: 5.4594x; 1.6118x over previous
#include <cuda_runtime.h>
#include <cuda_fp16.h>
#include <math_constants.h>
#include <cstdint>

// Shapes
#define BB 4
#define TQ 1024
#define DMODEL 2048
#define NHEADS 16
#define HDIM 128
#define CACHE 1024
#define MROWS (BB*TQ)          // 4096
#define INV_SCALE 0.08838834764831843f  // 1/sqrt(128)

#define OUT_ELEMS   (BB*TQ*DMODEL)
#define NEWK_OFF    OUT_ELEMS
#define NEWV_OFF    (OUT_ELEMS + BB*2048*DMODEL)

// Scratch
__device__ float  g_qproj[MROWS*DMODEL];           // Q proj (fp32, tf32-rounded)
__device__ __half g_attnh[MROWS*DMODEL];           // attention out (fp16)
__device__ __half g_qh [MROWS*DMODEL];             // fp16 activations
__device__ __half g_kh [MROWS*DMODEL];
__device__ __half g_vh [MROWS*DMODEL];
__device__ float  g_ckr[BB*CACHE*DMODEL];          // tf32-rounded caches (attention)
__device__ float  g_cvr[BB*CACHE*DMODEL];
__device__ __half g_wqh[DMODEL*DMODEL];            // fp16 weights
__device__ __half g_wkh[DMODEL*DMODEL];
__device__ __half g_wvh[DMODEL*DMODEL];
__device__ __half g_woh[DMODEL*DMODEL];

__device__ __forceinline__ uint32_t smem_u32(const void* p) {
    uint32_t a;
    asm("{ .reg .u64 t; cvta.to.shared.u64 t, %1; cvt.u32.u64 %0, t; }"
        : "=r"(a) : "l"(p));
    return a;
}
__device__ __forceinline__ void cp_async16(uint32_t dst, const void* src) {
    asm volatile("cp.async.cg.shared.global [%0], [%1], 16;" :: "r"(dst), "l"(src));
}
#define CP_COMMIT() asm volatile("cp.async.commit_group;" ::: "memory")
#define CP_WAIT2()  asm volatile("cp.async.wait_group 2;" ::: "memory")
#define CP_WAIT0()  asm volatile("cp.async.wait_group 0;" ::: "memory")

__device__ __forceinline__ uint32_t f2tf32(float f) {
    uint32_t r;
    asm("cvt.rna.tf32.f32 %0, %1;" : "=r"(r) : "f"(f));
    return r;
}
__device__ __forceinline__ float tf32f(float f) { return __uint_as_float(f2tf32(f)); }

__device__ __forceinline__ void mma_tf32(float& d0, float& d1, float& d2, float& d3,
                                         uint32_t a0, uint32_t a1, uint32_t a2, uint32_t a3,
                                         uint32_t b0, uint32_t b1)
{
    asm volatile(
        "mma.sync.aligned.m16n8k8.row.col.f32.tf32.tf32.f32 "
        "{%0,%1,%2,%3}, {%4,%5,%6,%7}, {%8,%9}, {%0,%1,%2,%3};"
        : "+f"(d0), "+f"(d1), "+f"(d2), "+f"(d3)
        : "r"(a0), "r"(a1), "r"(a2), "r"(a3), "r"(b0), "r"(b1));
}
__device__ __forceinline__ void mma_f16(float& d0, float& d1, float& d2, float& d3,
                                        uint32_t a0, uint32_t a1, uint32_t a2, uint32_t a3,
                                        uint32_t b0, uint32_t b1)
{
    asm volatile(
        "mma.sync.aligned.m16n8k16.row.col.f32.f16.f16.f32 "
        "{%0,%1,%2,%3}, {%4,%5,%6,%7}, {%8,%9}, {%0,%1,%2,%3};"
        : "+f"(d0), "+f"(d1), "+f"(d2), "+f"(d3)
        : "r"(a0), "r"(a1), "r"(a2), "r"(a3), "r"(b0), "r"(b1));
}

// ===========================================================================
// prep kernels
// ===========================================================================
// fp32 -> fp16, 8 elems/thread. grid.y selects array.
__global__ void conv3_kernel(const float* i0, __half* o0, const float* i1, __half* o1,
                             const float* i2, __half* o2)
{
    int idx = blockIdx.x * blockDim.x + threadIdx.x;
    const float* in; __half* out;
    switch (blockIdx.y) {
        case 0: in = i0; out = o0; break;
        case 1: in = i1; out = o1; break;
        default: in = i2; out = o2; break;
    }
    float4 v0 = ((const float4*)in)[2*idx];
    float4 v1 = ((const float4*)in)[2*idx+1];
    __half2 h[4];
    h[0] = __floats2half2_rn(v0.x, v0.y);
    h[1] = __floats2half2_rn(v0.z, v0.w);
    h[2] = __floats2half2_rn(v1.x, v1.y);
    h[3] = __floats2half2_rn(v1.z, v1.w);
    ((uint4*)out)[idx] = *(const uint4*)h;
}
__global__ void conv4_kernel(const float* i0, __half* o0, const float* i1, __half* o1,
                             const float* i2, __half* o2, const float* i3, __half* o3)
{
    int idx = blockIdx.x * blockDim.x + threadIdx.x;
    const float* in; __half* out;
    switch (blockIdx.y) {
        case 0: in = i0; out = o0; break;
        case 1: in = i1; out = o1; break;
        case 2: in = i2; out = o2; break;
        default: in = i3; out = o3; break;
    }
    float4 v0 = ((const float4*)in)[2*idx];
    float4 v1 = ((const float4*)in)[2*idx+1];
    __half2 h[4];
    h[0] = __floats2half2_rn(v0.x, v0.y);
    h[1] = __floats2half2_rn(v0.z, v0.w);
    h[2] = __floats2half2_rn(v1.x, v1.y);
    h[3] = __floats2half2_rn(v1.z, v1.w);
    ((uint4*)out)[idx] = *(const uint4*)h;
}
// fp32 -> tf32-rounded fp32 (attention caches)
__global__ void round2_kernel(const float* i0, float* o0, const float* i1, float* o1)
{
    int idx = blockIdx.x * blockDim.x + threadIdx.x;
    const float* in = blockIdx.y ? i1 : i0;
    float* out = blockIdx.y ? o1 : o0;
    float4 v = ((const float4*)in)[idx];
    v.x = tf32f(v.x); v.y = tf32f(v.y); v.z = tf32f(v.z); v.w = tf32f(v.w);
    ((float4*)out)[idx] = v;
}

// ===========================================================================
// fp16 mma.sync GEMM: CTA 128x256, warp tile 64x64, BK=64 (fp16), 4-stage
// cp.async, single barrier per k-iter, register double-buffered fragments.
// Epilogues fp32: normal (scale + tf32 round) or permuted K/V scatter.
// ===========================================================================
#define BK 64                                 // fp16 elements
#define STAGES 4
#define RS32 36                               // u32 per smem row (32 data + 4 pad)
#define STAGE_ROWS 384                        // A 0..127, B 128..383
#define STAGE_U32 (STAGE_ROWS*RS32)           // 13824
#define STAGE_BYTES (STAGE_U32*4)             // 55296
#define GEMM_SMEM  (STAGES*STAGE_BYTES)       // 221184
#define NITERS (2048/BK)                      // 32

struct GemmSet { const __half *A, *W; const float* bias; float *C; float scale; int round_out; int permute_out; };

__global__ __launch_bounds__(256, 1)
void gemm_f16(GemmSet s0, GemmSet s1, GemmSet s2)
{
    const GemmSet& S = (blockIdx.z == 0) ? s0 : (blockIdx.z == 1) ? s1 : s2;
    const __half* __restrict__ A = S.A;
    const __half* __restrict__ W = S.W;
    const float* __restrict__ bias = S.bias;
    float* __restrict__ C = S.C;

    extern __shared__ __align__(128) uint32_t smem[];
    const uint32_t smem_addr = smem_u32(smem);
    const int tid  = threadIdx.x;
    const int wid  = tid >> 5;
    const int lane = tid & 31;
    const int bm = blockIdx.y * 128;
    const int bn = blockIdx.x * 256;
    const int wm = (wid & 1) * 64;
    const int wn = (wid >> 1) * 64;

    auto load_stage = [&](int it) {
        const int s  = it & (STAGES - 1);
        const int k0 = it * BK;
        const uint32_t sbase = smem_addr + s * STAGE_BYTES;
        const __half* Ab = A + (size_t)bm * 2048 + k0;
        const __half* Wb = W + (size_t)bn * 2048 + k0;
#pragma unroll
        for (int c = 0; c < 4; c++) {            // A: 1024 x 16B chunks
            int id = tid + c * 256;
            int row = id >> 3, seg = id & 7;
            cp_async16(sbase + (row * RS32 + seg * 4) * 4,
                       Ab + (size_t)row * 2048 + seg * 8);
        }
#pragma unroll
        for (int c = 0; c < 8; c++) {            // B: 2048 x 16B chunks
            int id = tid + c * 256;
            int row = id >> 3, seg = id & 7;
            cp_async16(sbase + ((128 + row) * RS32 + seg * 4) * 4,
                       Wb + (size_t)row * 2048 + seg * 8);
        }
    };

    float acc[4][8][4];
#pragma unroll
    for (int mf = 0; mf < 4; mf++)
#pragma unroll
        for (int nf = 0; nf < 8; nf++)
#pragma unroll
            for (int r = 0; r < 4; r++) acc[mf][nf][r] = 0.f;

    load_stage(0); CP_COMMIT();
    load_stage(1); CP_COMMIT();
    load_stage(2); CP_COMMIT();

    const int lr = lane >> 2;
    const int lc = lane & 3;

    uint32_t afr[2][4][4], bfr[2][8][2];

    auto load_frags = [&](const uint32_t* As32, const uint32_t* Bs32, int ks,
                          uint32_t (&af)[4][4], uint32_t (&bf)[8][2]) {
        const int kb = ks * 8;                   // u32 units within row
#pragma unroll
        for (int nf = 0; nf < 8; nf++) {
            const uint32_t* bp = Bs32 + (wn + nf*8 + lr) * RS32 + kb + lc;
            bf[nf][0] = bp[0];
            bf[nf][1] = bp[4];
        }
#pragma unroll
        for (int mf = 0; mf < 4; mf++) {
            const uint32_t* ap = As32 + (wm + mf*16 + lr) * RS32 + kb + lc;
            af[mf][0] = ap[0];
            af[mf][1] = ap[8*RS32];
            af[mf][2] = ap[4];
            af[mf][3] = ap[8*RS32 + 4];
        }
    };

    for (int i = 0; i < NITERS; i++) {
        CP_WAIT2();               // stage i resident
        __syncthreads();          // everyone done reading buf (i-1)&3
        if (i + 3 < NITERS) load_stage(i + 3);
        CP_COMMIT();              // uniform group count

        const uint32_t* As32 = smem + (size_t)(i & (STAGES-1)) * STAGE_U32;
        const uint32_t* Bs32 = As32 + 128 * RS32;

        load_frags(As32, Bs32, 0, afr[0], bfr[0]);
#pragma unroll
        for (int ks = 0; ks < 4; ks++) {         // 4 x k16 steps
            const int cur = ks & 1;
            if (ks < 3) load_frags(As32, Bs32, ks + 1, afr[cur^1], bfr[cur^1]);
#pragma unroll
            for (int mf = 0; mf < 4; mf++)
#pragma unroll
                for (int nf = 0; nf < 8; nf++)
                    mma_f16(acc[mf][nf][0], acc[mf][nf][1],
                            acc[mf][nf][2], acc[mf][nf][3],
                            afr[cur][mf][0], afr[cur][mf][1],
                            afr[cur][mf][2], afr[cur][mf][3],
                            bfr[cur][nf][0], bfr[cur][nf][1]);
        }
    }

    if (S.permute_out) {
        // scatter into new_k/new_v layout: row = b*1024+tq, col = c ->
        // i = (c>>7)<<7 | 64 | (tq>>4), j = (tq&15)<<7 | (c&127)
#pragma unroll
        for (int nf = 0; nf < 8; nf++) {
            const int col = bn + wn + nf*8 + lc*2;
            const float b0 = bias[col], b1 = bias[col + 1];
            const int ch = (col >> 7) << 7;
            const int cl = col & 127;
#pragma unroll
            for (int mf = 0; mf < 4; mf++) {
                const int row0 = bm + wm + mf*16 + lr;
#pragma unroll
                for (int rr = 0; rr < 2; rr++) {
                    const int row = row0 + rr*8;
                    const int bb = row >> 10, tq = row & 1023;
                    const int ii = ch | 64 | (tq >> 4);
                    const int jj = ((tq & 15) << 7) | cl;
                    float v0 = acc[mf][nf][rr*2+0] + b0;
                    float v1 = acc[mf][nf][rr*2+1] + b1;
                    *(float2*)(C + (((size_t)((bb << 11) | ii)) << 11) + jj) =
                        make_float2(v0, v1);
                }
            }
        }
    } else {
        const float scale = S.scale;
        const int round_out = S.round_out;
#pragma unroll
        for (int nf = 0; nf < 8; nf++) {
            const int col = bn + wn + nf*8 + lc*2;
            const float b0 = bias[col], b1 = bias[col + 1];
#pragma unroll
            for (int mf = 0; mf < 4; mf++) {
                const int row0 = bm + wm + mf*16 + lr;
                float v0 = (acc[mf][nf][0] + b0) * scale;
                float v1 = (acc[mf][nf][1] + b1) * scale;
                float v2 = (acc[mf][nf][2] + b0) * scale;
                float v3 = (acc[mf][nf][3] + b1) * scale;
                if (round_out) { v0 = tf32f(v0); v1 = tf32f(v1); v2 = tf32f(v2); v3 = tf32f(v3); }
                *(float2*)(C + (size_t)row0 * 2048 + col)       = make_float2(v0, v1);
                *(float2*)(C + (size_t)(row0 + 8) * 2048 + col) = make_float2(v2, v3);
            }
        }
    }
}

// ===========================================================================
// Tensor-core flash attention (tf32 mma), causal over cache only.
// Output now emitted as fp16 (feeds fp16 O-projection).
// ===========================================================================
#define AQ_STRIDE 132
#define AK_STRIDE 132
#define AV_STRIDE 136
#define AP_STRIDE 68
#define AQS 0
#define AKS (64*AQ_STRIDE)
#define AVS (AKS + 2*64*AK_STRIDE)
#define APS (AVS + 2*64*AV_STRIDE)
#define ATTN_FLOATS (APS + 64*AP_STRIDE)   // 47104 floats -> 188416 B

__global__ __launch_bounds__(128, 1)
void attn_mma(const float* __restrict__ Q,
              const float* __restrict__ K,
              const float* __restrict__ V,
              __half* __restrict__ O)
{
    extern __shared__ __align__(128) float sm[];
    const uint32_t smaddr = smem_u32(sm);
    const int tid = threadIdx.x;
    const int w = tid >> 5, lane = tid & 31;
    const int lr = lane >> 2, lc = lane & 3;
    const int qb = gridDim.x - 1 - blockIdx.x;   // big tiles first
    const int bh = blockIdx.y;
    const int b = bh >> 4, h = bh & 15;
    const int q0 = qb * 64;
    const int nt = qb + 1;

    const float* Qg = Q + ((size_t)b*TQ + q0)*DMODEL + h*HDIM;
    const float* Kg = K + (size_t)b*CACHE*DMODEL + h*HDIM;
    const float* Vg = V + (size_t)b*CACHE*DMODEL + h*HDIM;

#pragma unroll
    for (int c = 0; c < 16; c++) {
        int id = tid + c*128;
        int row = id >> 5, c4 = (id & 31) << 2;
        float4 v = *(const float4*)(Qg + (size_t)row*2048 + c4);
        *(float4*)&sm[AQS + row*AQ_STRIDE + c4] = v;
    }

    auto load_kv = [&](int it) {
        const int s = it & 1;
        const int kv0 = it * 64;
        const uint32_t kd = smaddr + (AKS + s*64*AK_STRIDE)*4;
        const uint32_t vd = smaddr + (AVS + s*64*AV_STRIDE)*4;
        const float* Kt = Kg + (size_t)kv0*2048;
        const float* Vt = Vg + (size_t)kv0*2048;
#pragma unroll
        for (int c = 0; c < 16; c++) {
            int id = tid + c*128;
            int row = id >> 5, seg = id & 31;
            cp_async16(kd + row*(AK_STRIDE*4) + seg*16, Kt + (size_t)row*2048 + seg*4);
        }
#pragma unroll
        for (int c = 0; c < 16; c++) {
            int id = tid + c*128;
            int row = id >> 5, seg = id & 31;
            cp_async16(vd + row*(AV_STRIDE*4) + seg*16, Vt + (size_t)row*2048 + seg*4);
        }
    };

    load_kv(0); CP_COMMIT();

    float m0 = -1e30f, m1 = -1e30f, l0 = 0.f, l1 = 0.f;
    float oacc[16][4];
#pragma unroll
    for (int nf = 0; nf < 16; nf++)
#pragma unroll
        for (int r = 0; r < 4; r++) oacc[nf][r] = 0.f;

    const int qrow0 = q0 + w*16 + lr;

    for (int i = 0; i < nt; i++) {
        CP_WAIT0();
        __syncthreads();
        if (i + 1 < nt) { load_kv(i + 1); CP_COMMIT(); }

        // ---- S = Q K^T (pre-scaled) ----
        const float* Kb = sm + AKS + (i & 1)*64*AK_STRIDE;
        const float* Qw = sm + AQS + w*16*AQ_STRIDE;
        float sacc[8][4];
#pragma unroll
        for (int nf = 0; nf < 8; nf++)
#pragma unroll
            for (int r = 0; r < 4; r++) sacc[nf][r] = 0.f;

#pragma unroll
        for (int kb = 0; kb < 16; kb++) {
            const float* ap = Qw + lr*AQ_STRIDE + kb*8 + lc;
            uint32_t a0 = __float_as_uint(ap[0]);
            uint32_t a1 = __float_as_uint(ap[8*AQ_STRIDE]);
            uint32_t a2 = __float_as_uint(ap[4]);
            uint32_t a3 = __float_as_uint(ap[8*AQ_STRIDE + 4]);
#pragma unroll
            for (int nf = 0; nf < 8; nf++) {
                const float* bp = Kb + (nf*8 + lr)*AK_STRIDE + kb*8 + lc;
                mma_tf32(sacc[nf][0], sacc[nf][1], sacc[nf][2], sacc[nf][3],
                         a0, a1, a2, a3,
                         __float_as_uint(bp[0]), __float_as_uint(bp[4]));
            }
        }

        // ---- causal mask (diag tile only) ----
        const int kvb = i*64;
        if (i == qb) {
#pragma unroll
            for (int nf = 0; nf < 8; nf++) {
                int col = kvb + nf*8 + 2*lc;
                if (col     > qrow0)     sacc[nf][0] = -1e30f;
                if (col + 1 > qrow0)     sacc[nf][1] = -1e30f;
                if (col     > qrow0 + 8) sacc[nf][2] = -1e30f;
                if (col + 1 > qrow0 + 8) sacc[nf][3] = -1e30f;
            }
        }

        // ---- online softmax ----
        float mx0 = -1e30f, mx1 = -1e30f;
#pragma unroll
        for (int nf = 0; nf < 8; nf++) {
            mx0 = fmaxf(mx0, fmaxf(sacc[nf][0], sacc[nf][1]));
            mx1 = fmaxf(mx1, fmaxf(sacc[nf][2], sacc[nf][3]));
        }
        mx0 = fmaxf(mx0, __shfl_xor_sync(0xffffffffu, mx0, 1));
        mx0 = fmaxf(mx0, __shfl_xor_sync(0xffffffffu, mx0, 2));
        mx1 = fmaxf(mx1, __shfl_xor_sync(0xffffffffu, mx1, 1));
        mx1 = fmaxf(mx1, __shfl_xor_sync(0xffffffffu, mx1, 2));
        float mn0 = fmaxf(m0, mx0), mn1 = fmaxf(m1, mx1);
        float al0 = __expf(m0 - mn0), al1 = __expf(m1 - mn1);
        m0 = mn0; m1 = mn1;

        float* Pw = sm + APS + (w*16)*AP_STRIDE;
        float rs0 = 0.f, rs1 = 0.f;
#pragma unroll
        for (int nf = 0; nf < 8; nf++) {
            float p0 = __expf(sacc[nf][0] - mn0);
            float p1 = __expf(sacc[nf][1] - mn0);
            float p2 = __expf(sacc[nf][2] - mn1);
            float p3 = __expf(sacc[nf][3] - mn1);
            rs0 += p0 + p1; rs1 += p2 + p3;
            *(float2*)&Pw[lr*AP_STRIDE + nf*8 + 2*lc]     = make_float2(tf32f(p0), tf32f(p1));
            *(float2*)&Pw[(lr+8)*AP_STRIDE + nf*8 + 2*lc] = make_float2(tf32f(p2), tf32f(p3));
        }
        rs0 += __shfl_xor_sync(0xffffffffu, rs0, 1);
        rs0 += __shfl_xor_sync(0xffffffffu, rs0, 2);
        rs1 += __shfl_xor_sync(0xffffffffu, rs1, 1);
        rs1 += __shfl_xor_sync(0xffffffffu, rs1, 2);
        l0 = l0*al0 + rs0; l1 = l1*al1 + rs1;
#pragma unroll
        for (int nf = 0; nf < 16; nf++) {
            oacc[nf][0] *= al0; oacc[nf][1] *= al0;
            oacc[nf][2] *= al1; oacc[nf][3] *= al1;
        }
        __syncwarp();

        // ---- O += P @ V ----
        const float* Vb = sm + AVS + (i & 1)*64*AV_STRIDE;
#pragma unroll
        for (int kb = 0; kb < 8; kb++) {
            const float* ap = Pw + lr*AP_STRIDE + kb*8 + lc;
            uint32_t a0 = __float_as_uint(ap[0]);
            uint32_t a1 = __float_as_uint(ap[8*AP_STRIDE]);
            uint32_t a2 = __float_as_uint(ap[4]);
            uint32_t a3 = __float_as_uint(ap[8*AP_STRIDE + 4]);
#pragma unroll
            for (int nf = 0; nf < 16; nf++) {
                const float* bp = Vb + (kb*8 + lc)*AV_STRIDE + nf*8 + lr;
                mma_tf32(oacc[nf][0], oacc[nf][1], oacc[nf][2], oacc[nf][3],
                         a0, a1, a2, a3,
                         __float_as_uint(bp[0]), __float_as_uint(bp[4*AV_STRIDE]));
            }
        }
    }

    float inv0 = 1.f / l0, inv1 = 1.f / l1;
    __half* Ob = O + ((size_t)b*TQ + q0 + w*16)*DMODEL + h*HDIM;
#pragma unroll
    for (int nf = 0; nf < 16; nf++) {
        int col = nf*8 + 2*lc;
        *(__half2*)(Ob + (size_t)lr*2048 + col) =
            __floats2half2_rn(oacc[nf][0]*inv0, oacc[nf][1]*inv0);
        *(__half2*)(Ob + (size_t)(lr+8)*2048 + col) =
            __floats2half2_rn(oacc[nf][2]*inv1, oacc[nf][3]*inv1);
    }
}

// ---------------------------------------------------------------------------
// new_k / new_v permute, cache half only. Proj half written by K/V GEMMs.
// ---------------------------------------------------------------------------
__global__ void permute_cache(const float* __restrict__ cache,
                              float* __restrict__ out)
{
    int idx = blockIdx.x * blockDim.x + threadIdx.x;   // float4 chunks: 4*1024*512
    int j4  = idx & 511;
    int rem = idx >> 9;
    int ip  = rem & 1023;
    int b   = rem >> 10;
    int il  = ip & 63, ih = ip >> 6;
    int i   = (ih << 7) | il;
    int j   = j4 << 2;
    int t   = il*16 + (j >> 7);
    int c   = (ih << 7) | (j & 127);
    float4 v = *(const float4*)(cache + ((size_t)b*CACHE + t)*DMODEL + c);
    *(float4*)(out + (((size_t)((b << 11) | i)) << 11) + j) = v;
}

// ---------------------------------------------------------------------------
extern "C" void kernel_launch(void* const* d_in, const int* in_sizes, int n_in,
                              void* d_out, int out_size)
{
    const float* query  = (const float*)d_in[0];
    const float* key    = (const float*)d_in[1];
    const float* value  = (const float*)d_in[2];
    const float* cachek = (const float*)d_in[3];
    const float* cachev = (const float*)d_in[4];
    const float* Wq = (const float*)d_in[5];  const float* bq = (const float*)d_in[6];
    const float* Wk = (const float*)d_in[7];  const float* bk = (const float*)d_in[8];
    const float* Wv = (const float*)d_in[9];  const float* bv = (const float*)d_in[10];
    const float* Wo = (const float*)d_in[11]; const float* bo = (const float*)d_in[12];
    float* out = (float*)d_out;

    float *qp, *ckr, *cvr;
    __half *ah, *qh, *kh, *vh, *wqh, *wkh, *wvh, *woh;
    cudaGetSymbolAddress((void**)&qp,  g_qproj);
    cudaGetSymbolAddress((void**)&ah,  g_attnh);
    cudaGetSymbolAddress((void**)&qh,  g_qh);
    cudaGetSymbolAddress((void**)&kh,  g_kh);
    cudaGetSymbolAddress((void**)&vh,  g_vh);
    cudaGetSymbolAddress((void**)&ckr, g_ckr);
    cudaGetSymbolAddress((void**)&cvr, g_cvr);
    cudaGetSymbolAddress((void**)&wqh, g_wqh);
    cudaGetSymbolAddress((void**)&wkh, g_wkh);
    cudaGetSymbolAddress((void**)&wvh, g_wvh);
    cudaGetSymbolAddress((void**)&woh, g_woh);

    // prep
    const int ACT8 = MROWS*DMODEL/8;        // 1048576
    const int W8   = DMODEL*DMODEL/8;       // 524288
    const int ACT4 = MROWS*DMODEL/4;        // 2097152
    conv3_kernel<<<dim3(ACT8/256, 3), 256>>>(query, qh, key, kh, value, vh);
    conv4_kernel<<<dim3(W8/256, 4), 256>>>(Wq, wqh, Wk, wkh, Wv, wvh, Wo, woh);
    round2_kernel<<<dim3(ACT4/256, 2), 256>>>(cachek, ckr, cachev, cvr);

    cudaFuncSetAttribute(gemm_f16, cudaFuncAttributeMaxDynamicSharedMemorySize, GEMM_SMEM);

    // merged QKV projections (grid.z = 3); K/V scatter straight into new_k/new_v
    GemmSet sq{qh, wqh, bq, qp,              INV_SCALE, 1, 0};
    GemmSet sk{kh, wkh, bk, out + NEWK_OFF,  1.f,       0, 1};
    GemmSet sv{vh, wvh, bv, out + NEWV_OFF,  1.f,       0, 1};
    gemm_f16<<<dim3(8, 32, 3), 256, GEMM_SMEM>>>(sq, sk, sv);

    cudaFuncSetAttribute(attn_mma, cudaFuncAttributeMaxDynamicSharedMemorySize,
                         ATTN_FLOATS*4);
    attn_mma<<<dim3(TQ/64, BB*NHEADS), 128, ATTN_FLOATS*4>>>(qp, ckr, cvr, ah);

    // O projection (fp16 A from attention)
    GemmSet so{ah, woh, bo, out, 1.f, 0, 0};
    gemm_f16<<<dim3(8, 32, 1), 256, GEMM_SMEM>>>(so, so, so);

    // cache halves of new_k / new_v
    permute_cache<<<2097152/256, 256>>>(cachek, out + NEWK_OFF);
    permute_cache<<<2097152/256, 256>>>(cachev, out + NEWV_OFF);
}

// round 12
// speedup vs baseline: 6.1655x; 1.1293x over previous
#include <cuda_runtime.h>
#include <cuda_fp16.h>
#include <math_constants.h>
#include <cstdint>

// Shapes
#define BB 4
#define TQ 1024
#define DMODEL 2048
#define NHEADS 16
#define HDIM 128
#define CACHE 1024
#define MROWS (BB*TQ)          // 4096
#define INV_SCALE 0.08838834764831843f  // 1/sqrt(128)

#define OUT_ELEMS   (BB*TQ*DMODEL)
#define NEWK_OFF    OUT_ELEMS
#define NEWV_OFF    (OUT_ELEMS + BB*2048*DMODEL)

// Scratch
__device__ __half g_qph  [MROWS*DMODEL];          // Q proj (fp16, pre-scaled)
__device__ __half g_attnh[MROWS*DMODEL];          // attention out (fp16)
__device__ __half g_qh [MROWS*DMODEL];            // fp16 activations
__device__ __half g_kh [MROWS*DMODEL];
__device__ __half g_vh [MROWS*DMODEL];
__device__ __half g_ckh[BB*CACHE*DMODEL];         // fp16 K cache [b][t][d]
__device__ __half g_cvt[BB*NHEADS*HDIM*CACHE];    // fp16 V cache transposed [bh][d][t]
__device__ __half g_wqh[DMODEL*DMODEL];           // fp16 weights
__device__ __half g_wkh[DMODEL*DMODEL];
__device__ __half g_wvh[DMODEL*DMODEL];
__device__ __half g_woh[DMODEL*DMODEL];

__device__ __forceinline__ uint32_t smem_u32(const void* p) {
    uint32_t a;
    asm("{ .reg .u64 t; cvta.to.shared.u64 t, %1; cvt.u32.u64 %0, t; }"
        : "=r"(a) : "l"(p));
    return a;
}
__device__ __forceinline__ void cp_async16(uint32_t dst, const void* src) {
    asm volatile("cp.async.cg.shared.global [%0], [%1], 16;" :: "r"(dst), "l"(src));
}
#define CP_COMMIT() asm volatile("cp.async.commit_group;" ::: "memory")
#define CP_WAIT2()  asm volatile("cp.async.wait_group 2;" ::: "memory")
#define CP_WAIT0()  asm volatile("cp.async.wait_group 0;" ::: "memory")

__device__ __forceinline__ void mma_f16(float& d0, float& d1, float& d2, float& d3,
                                        uint32_t a0, uint32_t a1, uint32_t a2, uint32_t a3,
                                        uint32_t b0, uint32_t b1)
{
    asm volatile(
        "mma.sync.aligned.m16n8k16.row.col.f32.f16.f16.f32 "
        "{%0,%1,%2,%3}, {%4,%5,%6,%7}, {%8,%9}, {%0,%1,%2,%3};"
        : "+f"(d0), "+f"(d1), "+f"(d2), "+f"(d3)
        : "r"(a0), "r"(a1), "r"(a2), "r"(a3), "r"(b0), "r"(b1));
}

// ===========================================================================
// prep kernels
// ===========================================================================
__global__ void conv4_kernel(const float* i0, __half* o0, const float* i1, __half* o1,
                             const float* i2, __half* o2, const float* i3, __half* o3)
{
    int idx = blockIdx.x * blockDim.x + threadIdx.x;
    const float* in; __half* out;
    switch (blockIdx.y) {
        case 0: in = i0; out = o0; break;
        case 1: in = i1; out = o1; break;
        case 2: in = i2; out = o2; break;
        default: in = i3; out = o3; break;
    }
    float4 v0 = ((const float4*)in)[2*idx];
    float4 v1 = ((const float4*)in)[2*idx+1];
    __half2 h[4];
    h[0] = __floats2half2_rn(v0.x, v0.y);
    h[1] = __floats2half2_rn(v0.z, v0.w);
    h[2] = __floats2half2_rn(v1.x, v1.y);
    h[3] = __floats2half2_rn(v1.z, v1.w);
    ((uint4*)out)[idx] = *(const uint4*)h;
}

// V cache: fp32 [b][t][2048] -> fp16 transposed per head [bh][d (128)][t (1024)]
__global__ void transpose_v_kernel(const float* __restrict__ cachev,
                                   __half* __restrict__ vt)
{
    __shared__ float tile[32][33];
    const int tx = threadIdx.x, ty = threadIdx.y;   // (32, 8)
    const int t0 = blockIdx.x * 32;
    const int d0 = blockIdx.y * 32;
    const int bh = blockIdx.z;
    const int b = bh >> 4, h = bh & 15;
#pragma unroll
    for (int dt = 0; dt < 4; dt++) {
        int t = t0 + ty + dt*8;
        tile[ty + dt*8][tx] =
            cachev[((size_t)b*CACHE + t)*DMODEL + h*HDIM + d0 + tx];
    }
    __syncthreads();
#pragma unroll
    for (int dt = 0; dt < 4; dt++) {
        int d = d0 + ty + dt*8;
        vt[(size_t)bh*HDIM*CACHE + (size_t)d*CACHE + t0 + tx] =
            __float2half_rn(tile[tx][ty + dt*8]);
    }
}

// ===========================================================================
// fp16 mma.sync GEMM: CTA 128x256, warp tile 64x64, BK=64 (fp16), 4-stage
// cp.async, single barrier per k-iter, register double-buffered fragments.
// Epilogues fp32/fp16/permuted-scatter.
// ===========================================================================
#define BK 64
#define STAGES 4
#define RS32 36
#define STAGE_ROWS 384
#define STAGE_U32 (STAGE_ROWS*RS32)
#define STAGE_BYTES (STAGE_U32*4)
#define GEMM_SMEM  (STAGES*STAGE_BYTES)       // 221184
#define NITERS (2048/BK)                      // 32

// out_mode: 0 = fp32 store, 1 = fp16 store (scaled), 2 = permuted fp32 scatter
struct GemmSet { const __half *A, *W; const float* bias; void *C; float scale; int out_mode; };

__global__ __launch_bounds__(256, 1)
void gemm_f16(GemmSet s0, GemmSet s1, GemmSet s2)
{
    const GemmSet& S = (blockIdx.z == 0) ? s0 : (blockIdx.z == 1) ? s1 : s2;
    const __half* __restrict__ A = S.A;
    const __half* __restrict__ W = S.W;
    const float* __restrict__ bias = S.bias;

    extern __shared__ __align__(128) uint32_t smem[];
    const uint32_t smem_addr = smem_u32(smem);
    const int tid  = threadIdx.x;
    const int wid  = tid >> 5;
    const int lane = tid & 31;
    const int bm = blockIdx.y * 128;
    const int bn = blockIdx.x * 256;
    const int wm = (wid & 1) * 64;
    const int wn = (wid >> 1) * 64;

    auto load_stage = [&](int it) {
        const int s  = it & (STAGES - 1);
        const int k0 = it * BK;
        const uint32_t sbase = smem_addr + s * STAGE_BYTES;
        const __half* Ab = A + (size_t)bm * 2048 + k0;
        const __half* Wb = W + (size_t)bn * 2048 + k0;
#pragma unroll
        for (int c = 0; c < 4; c++) {
            int id = tid + c * 256;
            int row = id >> 3, seg = id & 7;
            cp_async16(sbase + (row * RS32 + seg * 4) * 4,
                       Ab + (size_t)row * 2048 + seg * 8);
        }
#pragma unroll
        for (int c = 0; c < 8; c++) {
            int id = tid + c * 256;
            int row = id >> 3, seg = id & 7;
            cp_async16(sbase + ((128 + row) * RS32 + seg * 4) * 4,
                       Wb + (size_t)row * 2048 + seg * 8);
        }
    };

    float acc[4][8][4];
#pragma unroll
    for (int mf = 0; mf < 4; mf++)
#pragma unroll
        for (int nf = 0; nf < 8; nf++)
#pragma unroll
            for (int r = 0; r < 4; r++) acc[mf][nf][r] = 0.f;

    load_stage(0); CP_COMMIT();
    load_stage(1); CP_COMMIT();
    load_stage(2); CP_COMMIT();

    const int lr = lane >> 2;
    const int lc = lane & 3;

    uint32_t afr[2][4][4], bfr[2][8][2];

    auto load_frags = [&](const uint32_t* As32, const uint32_t* Bs32, int ks,
                          uint32_t (&af)[4][4], uint32_t (&bf)[8][2]) {
        const int kb = ks * 8;
#pragma unroll
        for (int nf = 0; nf < 8; nf++) {
            const uint32_t* bp = Bs32 + (wn + nf*8 + lr) * RS32 + kb + lc;
            bf[nf][0] = bp[0];
            bf[nf][1] = bp[4];
        }
#pragma unroll
        for (int mf = 0; mf < 4; mf++) {
            const uint32_t* ap = As32 + (wm + mf*16 + lr) * RS32 + kb + lc;
            af[mf][0] = ap[0];
            af[mf][1] = ap[8*RS32];
            af[mf][2] = ap[4];
            af[mf][3] = ap[8*RS32 + 4];
        }
    };

    for (int i = 0; i < NITERS; i++) {
        CP_WAIT2();
        __syncthreads();
        if (i + 3 < NITERS) load_stage(i + 3);
        CP_COMMIT();

        const uint32_t* As32 = smem + (size_t)(i & (STAGES-1)) * STAGE_U32;
        const uint32_t* Bs32 = As32 + 128 * RS32;

        load_frags(As32, Bs32, 0, afr[0], bfr[0]);
#pragma unroll
        for (int ks = 0; ks < 4; ks++) {
            const int cur = ks & 1;
            if (ks < 3) load_frags(As32, Bs32, ks + 1, afr[cur^1], bfr[cur^1]);
#pragma unroll
            for (int mf = 0; mf < 4; mf++)
#pragma unroll
                for (int nf = 0; nf < 8; nf++)
                    mma_f16(acc[mf][nf][0], acc[mf][nf][1],
                            acc[mf][nf][2], acc[mf][nf][3],
                            afr[cur][mf][0], afr[cur][mf][1],
                            afr[cur][mf][2], afr[cur][mf][3],
                            bfr[cur][nf][0], bfr[cur][nf][1]);
        }
    }

    if (S.out_mode == 2) {
        float* C = (float*)S.C;
#pragma unroll
        for (int nf = 0; nf < 8; nf++) {
            const int col = bn + wn + nf*8 + lc*2;
            const float b0 = bias[col], b1 = bias[col + 1];
            const int ch = (col >> 7) << 7;
            const int cl = col & 127;
#pragma unroll
            for (int mf = 0; mf < 4; mf++) {
                const int row0 = bm + wm + mf*16 + lr;
#pragma unroll
                for (int rr = 0; rr < 2; rr++) {
                    const int row = row0 + rr*8;
                    const int bb = row >> 10, tq = row & 1023;
                    const int ii = ch | 64 | (tq >> 4);
                    const int jj = ((tq & 15) << 7) | cl;
                    *(float2*)(C + (((size_t)((bb << 11) | ii)) << 11) + jj) =
                        make_float2(acc[mf][nf][rr*2+0] + b0,
                                    acc[mf][nf][rr*2+1] + b1);
                }
            }
        }
    } else if (S.out_mode == 1) {
        __half* C = (__half*)S.C;
        const float scale = S.scale;
#pragma unroll
        for (int nf = 0; nf < 8; nf++) {
            const int col = bn + wn + nf*8 + lc*2;
            const float b0 = bias[col], b1 = bias[col + 1];
#pragma unroll
            for (int mf = 0; mf < 4; mf++) {
                const int row0 = bm + wm + mf*16 + lr;
                *(__half2*)(C + (size_t)row0 * 2048 + col) =
                    __floats2half2_rn((acc[mf][nf][0] + b0) * scale,
                                      (acc[mf][nf][1] + b1) * scale);
                *(__half2*)(C + (size_t)(row0 + 8) * 2048 + col) =
                    __floats2half2_rn((acc[mf][nf][2] + b0) * scale,
                                      (acc[mf][nf][3] + b1) * scale);
            }
        }
    } else {
        float* C = (float*)S.C;
#pragma unroll
        for (int nf = 0; nf < 8; nf++) {
            const int col = bn + wn + nf*8 + lc*2;
            const float b0 = bias[col], b1 = bias[col + 1];
#pragma unroll
            for (int mf = 0; mf < 4; mf++) {
                const int row0 = bm + wm + mf*16 + lr;
                *(float2*)(C + (size_t)row0 * 2048 + col) =
                    make_float2(acc[mf][nf][0] + b0, acc[mf][nf][1] + b1);
                *(float2*)(C + (size_t)(row0 + 8) * 2048 + col) =
                    make_float2(acc[mf][nf][2] + b0, acc[mf][nf][3] + b1);
            }
        }
    }
}

// ===========================================================================
// fp16 tensor-core flash attention, causal over cache only.
// Q (fp16, pre-scaled) [64][128]; K fp16 [t][d]; V fp16 transposed [d][t].
// All smem in u32 units; strides 68 (Q/K rows, 128 halves) and 36 (Vt/P).
// ===========================================================================
#define QST 68
#define VST 36
#define AQS 0
#define AKS (64*QST)                       // 4352
#define AKSZ (64*QST)                      // per K buffer
#define AVTS (AKS + 2*AKSZ)                // 13056
#define AVSZ (128*VST)                     // 4608 per Vt buffer
#define APS (AVTS + 2*AVSZ)                // 22272
#define ATTN_U32 (APS + 64*VST)            // 24576 -> 98304 B

__global__ __launch_bounds__(128, 1)
void attn_mma(const __half* __restrict__ Q,
              const __half* __restrict__ K,
              const __half* __restrict__ Vt,
              __half* __restrict__ O)
{
    extern __shared__ __align__(128) uint32_t sm[];
    const uint32_t smaddr = smem_u32(sm);
    const int tid = threadIdx.x;
    const int w = tid >> 5, lane = tid & 31;
    const int lr = lane >> 2, lc = lane & 3;
    const int qb = gridDim.x - 1 - blockIdx.x;   // big tiles first
    const int bh = blockIdx.y;
    const int b = bh >> 4, h = bh & 15;
    const int q0 = qb * 64;
    const int nt = qb + 1;

    const __half* Qg  = Q  + ((size_t)b*TQ + q0)*DMODEL + h*HDIM;
    const __half* Kg  = K  + (size_t)b*CACHE*DMODEL + h*HDIM;
    const __half* Vtg = Vt + (size_t)bh*HDIM*CACHE;

    // Q tile: 64 rows x 128 halves (16 segs of 16B)
#pragma unroll
    for (int c = 0; c < 8; c++) {
        int id = tid + c*128;
        int row = id >> 4, seg = id & 15;
        cp_async16(smaddr + (AQS + row*QST + seg*4)*4,
                   Qg + (size_t)row*2048 + seg*8);
    }

    auto load_kv = [&](int it) {
        const int s = it & 1;
        const int kv0 = it * 64;
        const __half* Kt = Kg + (size_t)kv0*2048;
#pragma unroll
        for (int c = 0; c < 8; c++) {            // K: 64 rows x 16 segs
            int id = tid + c*128;
            int row = id >> 4, seg = id & 15;
            cp_async16(smaddr + (AKS + s*AKSZ + row*QST + seg*4)*4,
                       Kt + (size_t)row*2048 + seg*8);
        }
#pragma unroll
        for (int c = 0; c < 8; c++) {            // Vt: 128 rows x 8 segs (64 halves)
            int id = tid + c*128;
            int row = id >> 3, seg = id & 7;
            cp_async16(smaddr + (AVTS + s*AVSZ + row*VST + seg*4)*4,
                       Vtg + (size_t)row*CACHE + kv0 + seg*8);
        }
    };

    load_kv(0); CP_COMMIT();

    float m0 = -1e30f, m1 = -1e30f, l0 = 0.f, l1 = 0.f;
    float oacc[16][4];
#pragma unroll
    for (int nf = 0; nf < 16; nf++)
#pragma unroll
        for (int r = 0; r < 4; r++) oacc[nf][r] = 0.f;

    const int qrow0 = q0 + w*16 + lr;

    for (int i = 0; i < nt; i++) {
        CP_WAIT0();
        __syncthreads();
        if (i + 1 < nt) { load_kv(i + 1); CP_COMMIT(); }

        // ---- S = Q K^T (fp16, pre-scaled Q) ----
        const uint32_t* Kb = sm + AKS + (i & 1)*AKSZ;
        const uint32_t* Qw = sm + AQS + (w*16)*QST;
        float sacc[8][4];
#pragma unroll
        for (int nf = 0; nf < 8; nf++)
#pragma unroll
            for (int r = 0; r < 4; r++) sacc[nf][r] = 0.f;

#pragma unroll
        for (int kb = 0; kb < 8; kb++) {         // 8 x k16 over d=128
            const uint32_t* ap = Qw + lr*QST + kb*8 + lc;
            uint32_t a0 = ap[0];
            uint32_t a1 = ap[8*QST];
            uint32_t a2 = ap[4];
            uint32_t a3 = ap[8*QST + 4];
#pragma unroll
            for (int nf = 0; nf < 8; nf++) {
                const uint32_t* bp = Kb + (nf*8 + lr)*QST + kb*8 + lc;
                mma_f16(sacc[nf][0], sacc[nf][1], sacc[nf][2], sacc[nf][3],
                        a0, a1, a2, a3, bp[0], bp[4]);
            }
        }

        // ---- causal mask (diag tile only) ----
        const int kvb = i*64;
        if (i == qb) {
#pragma unroll
            for (int nf = 0; nf < 8; nf++) {
                int col = kvb + nf*8 + 2*lc;
                if (col     > qrow0)     sacc[nf][0] = -1e30f;
                if (col + 1 > qrow0)     sacc[nf][1] = -1e30f;
                if (col     > qrow0 + 8) sacc[nf][2] = -1e30f;
                if (col + 1 > qrow0 + 8) sacc[nf][3] = -1e30f;
            }
        }

        // ---- online softmax ----
        float mx0 = -1e30f, mx1 = -1e30f;
#pragma unroll
        for (int nf = 0; nf < 8; nf++) {
            mx0 = fmaxf(mx0, fmaxf(sacc[nf][0], sacc[nf][1]));
            mx1 = fmaxf(mx1, fmaxf(sacc[nf][2], sacc[nf][3]));
        }
        mx0 = fmaxf(mx0, __shfl_xor_sync(0xffffffffu, mx0, 1));
        mx0 = fmaxf(mx0, __shfl_xor_sync(0xffffffffu, mx0, 2));
        mx1 = fmaxf(mx1, __shfl_xor_sync(0xffffffffu, mx1, 1));
        mx1 = fmaxf(mx1, __shfl_xor_sync(0xffffffffu, mx1, 2));
        float mn0 = fmaxf(m0, mx0), mn1 = fmaxf(m1, mx1);
        float al0 = __expf(m0 - mn0), al1 = __expf(m1 - mn1);
        m0 = mn0; m1 = mn1;

        uint32_t* Pw = sm + APS + (w*16)*VST;
        float rs0 = 0.f, rs1 = 0.f;
#pragma unroll
        for (int nf = 0; nf < 8; nf++) {
            float p0 = __expf(sacc[nf][0] - mn0);
            float p1 = __expf(sacc[nf][1] - mn0);
            float p2 = __expf(sacc[nf][2] - mn1);
            float p3 = __expf(sacc[nf][3] - mn1);
            rs0 += p0 + p1; rs1 += p2 + p3;
            __half2 h01 = __floats2half2_rn(p0, p1);
            __half2 h23 = __floats2half2_rn(p2, p3);
            Pw[lr*VST + nf*4 + lc]     = *(const uint32_t*)&h01;
            Pw[(lr+8)*VST + nf*4 + lc] = *(const uint32_t*)&h23;
        }
        rs0 += __shfl_xor_sync(0xffffffffu, rs0, 1);
        rs0 += __shfl_xor_sync(0xffffffffu, rs0, 2);
        rs1 += __shfl_xor_sync(0xffffffffu, rs1, 1);
        rs1 += __shfl_xor_sync(0xffffffffu, rs1, 2);
        l0 = l0*al0 + rs0; l1 = l1*al1 + rs1;
#pragma unroll
        for (int nf = 0; nf < 16; nf++) {
            oacc[nf][0] *= al0; oacc[nf][1] *= al0;
            oacc[nf][2] *= al1; oacc[nf][3] *= al1;
        }
        __syncwarp();

        // ---- O += P @ V (Vt is [d][t] -> direct B fragments) ----
        const uint32_t* Vb = sm + AVTS + (i & 1)*AVSZ;
#pragma unroll
        for (int kb = 0; kb < 4; kb++) {         // 4 x k16 over kv=64
            const uint32_t* ap = Pw + lr*VST + kb*8 + lc;
            uint32_t a0 = ap[0];
            uint32_t a1 = ap[8*VST];
            uint32_t a2 = ap[4];
            uint32_t a3 = ap[8*VST + 4];
#pragma unroll
            for (int nf = 0; nf < 16; nf++) {
                const uint32_t* bp = Vb + (nf*8 + lr)*VST + kb*8 + lc;
                mma_f16(oacc[nf][0], oacc[nf][1], oacc[nf][2], oacc[nf][3],
                        a0, a1, a2, a3, bp[0], bp[4]);
            }
        }
    }

    float inv0 = 1.f / l0, inv1 = 1.f / l1;
    __half* Ob = O + ((size_t)b*TQ + q0 + w*16)*DMODEL + h*HDIM;
#pragma unroll
    for (int nf = 0; nf < 16; nf++) {
        int col = nf*8 + 2*lc;
        *(__half2*)(Ob + (size_t)lr*2048 + col) =
            __floats2half2_rn(oacc[nf][0]*inv0, oacc[nf][1]*inv0);
        *(__half2*)(Ob + (size_t)(lr+8)*2048 + col) =
            __floats2half2_rn(oacc[nf][2]*inv1, oacc[nf][3]*inv1);
    }
}

// ---------------------------------------------------------------------------
// new_k / new_v permute, cache half only, both tensors in one launch.
// ---------------------------------------------------------------------------
__global__ void permute_cache2(const float* __restrict__ cachek,
                               const float* __restrict__ cachev,
                               float* __restrict__ outk,
                               float* __restrict__ outv)
{
    const float* cache = blockIdx.y ? cachev : cachek;
    float* out = blockIdx.y ? outv : outk;
    int idx = blockIdx.x * blockDim.x + threadIdx.x;
    int j4  = idx & 511;
    int rem = idx >> 9;
    int ip  = rem & 1023;
    int b   = rem >> 10;
    int il  = ip & 63, ih = ip >> 6;
    int i   = (ih << 7) | il;
    int j   = j4 << 2;
    int t   = il*16 + (j >> 7);
    int c   = (ih << 7) | (j & 127);
    float4 v = *(const float4*)(cache + ((size_t)b*CACHE + t)*DMODEL + c);
    *(float4*)(out + (((size_t)((b << 11) | i)) << 11) + j) = v;
}

// ---------------------------------------------------------------------------
extern "C" void kernel_launch(void* const* d_in, const int* in_sizes, int n_in,
                              void* d_out, int out_size)
{
    const float* query  = (const float*)d_in[0];
    const float* key    = (const float*)d_in[1];
    const float* value  = (const float*)d_in[2];
    const float* cachek = (const float*)d_in[3];
    const float* cachev = (const float*)d_in[4];
    const float* Wq = (const float*)d_in[5];  const float* bq = (const float*)d_in[6];
    const float* Wk = (const float*)d_in[7];  const float* bk = (const float*)d_in[8];
    const float* Wv = (const float*)d_in[9];  const float* bv = (const float*)d_in[10];
    const float* Wo = (const float*)d_in[11]; const float* bo = (const float*)d_in[12];
    float* out = (float*)d_out;

    __half *qph, *ah, *qh, *kh, *vh, *ckh, *cvt, *wqh, *wkh, *wvh, *woh;
    cudaGetSymbolAddress((void**)&qph, g_qph);
    cudaGetSymbolAddress((void**)&ah,  g_attnh);
    cudaGetSymbolAddress((void**)&qh,  g_qh);
    cudaGetSymbolAddress((void**)&kh,  g_kh);
    cudaGetSymbolAddress((void**)&vh,  g_vh);
    cudaGetSymbolAddress((void**)&ckh, g_ckh);
    cudaGetSymbolAddress((void**)&cvt, g_cvt);
    cudaGetSymbolAddress((void**)&wqh, g_wqh);
    cudaGetSymbolAddress((void**)&wkh, g_wkh);
    cudaGetSymbolAddress((void**)&wvh, g_wvh);
    cudaGetSymbolAddress((void**)&woh, g_woh);

    // prep: fp16 conversions + V transpose
    const int ACT8 = MROWS*DMODEL/8;        // 1048576
    const int W8   = DMODEL*DMODEL/8;       // 524288
    conv4_kernel<<<dim3(ACT8/256, 4), 256>>>(query, qh, key, kh, value, vh,
                                             cachek, ckh);
    conv4_kernel<<<dim3(W8/256, 4), 256>>>(Wq, wqh, Wk, wkh, Wv, wvh, Wo, woh);
    transpose_v_kernel<<<dim3(CACHE/32, HDIM/32, BB*NHEADS), dim3(32, 8)>>>(cachev, cvt);

    cudaFuncSetAttribute(gemm_f16, cudaFuncAttributeMaxDynamicSharedMemorySize, GEMM_SMEM);

    // merged QKV projections; Q -> fp16 pre-scaled, K/V scatter into new_k/new_v
    GemmSet sq{qh, wqh, bq, qph,             INV_SCALE, 1};
    GemmSet sk{kh, wkh, bk, out + NEWK_OFF,  1.f,       2};
    GemmSet sv{vh, wvh, bv, out + NEWV_OFF,  1.f,       2};
    gemm_f16<<<dim3(8, 32, 3), 256, GEMM_SMEM>>>(sq, sk, sv);

    cudaFuncSetAttribute(attn_mma, cudaFuncAttributeMaxDynamicSharedMemorySize,
                         ATTN_U32*4);
    attn_mma<<<dim3(TQ/64, BB*NHEADS), 128, ATTN_U32*4>>>(qph, ckh, cvt, ah);

    // O projection (fp16 A from attention)
    GemmSet so{ah, woh, bo, out, 1.f, 0};
    gemm_f16<<<dim3(8, 32, 1), 256, GEMM_SMEM>>>(so, so, so);

    // cache halves of new_k / new_v
    permute_cache2<<<dim3(2097152/256, 2), 256>>>(cachek, cachev,
                                                  out + NEWK_OFF, out + NEWV_OFF);
}